// round 9
// baseline (speedup 1.0000x reference)
#include <cuda_runtime.h>
#include <cuda_bf16.h>
#include <stdint.h>
#include <math.h>

#define EPSF 1e-8f
#define DD 128               // d
#define KPAD 10048           // 314*32 padded K (= problem N)
#define NCHUNKS 157          // 64-k chunks
#define EPAD 5120
#define EPITCH 5120          // 40*128
#define NKS 7                // K splits

// ---------------- static device scratch (no allocation) ----------------------
static __device__ __align__(256) __nv_bfloat16 g_FsT[DD * KPAD];     // Fs^T K-major bf16
static __device__ __align__(256) float g_Mpart[NKS * DD * EPITCH];   // 18.35 MB partials
static __device__ float g_deinv[EPAD];
static __device__ float g_blocksum[64];
static __device__ float g_f2sum[320];
static __device__ int   g_tilecnt[64];
static __device__ int   g_donecnt;

// ---------------- helpers ----------------------------------------------------
__device__ __forceinline__ uint32_t smem_u32(const void* p) {
    uint32_t a;
    asm("{ .reg .u64 t; cvta.to.shared.u64 t, %1; cvt.u32.u64 %0, t; }"
        : "=r"(a) : "l"(p));
    return a;
}
#define SWZ(o) ((o) ^ (((o) >> 3) & 0x70))

__device__ __forceinline__ void sts128(uint32_t addr, uint32_t a, uint32_t b,
                                       uint32_t c, uint32_t d) {
    asm volatile("st.shared.v4.b32 [%0], {%1,%2,%3,%4};"
                 :: "r"(addr), "r"(a), "r"(b), "r"(c), "r"(d) : "memory");
}
#define CPA16(dst, src) \
    asm volatile("cp.async.ca.shared.global [%0], [%1], 16;" \
                 :: "r"(dst), "l"(src) : "memory")
#define CPA_COMMIT() asm volatile("cp.async.commit_group;" ::: "memory")
#define CPA_WAIT0()  asm volatile("cp.async.wait_group 0;" ::: "memory")

#define LDSM4(r, addr) \
    asm volatile("ldmatrix.sync.aligned.m8n8.x4.shared.b16 {%0,%1,%2,%3}, [%4];" \
                 : "=r"((r)[0]), "=r"((r)[1]), "=r"((r)[2]), "=r"((r)[3]) : "r"(addr))
#define LDSM4T(r, addr) \
    asm volatile("ldmatrix.sync.aligned.m8n8.x4.trans.shared.b16 {%0,%1,%2,%3}, [%4];" \
                 : "=r"((r)[0]), "=r"((r)[1]), "=r"((r)[2]), "=r"((r)[3]) : "r"(addr))

__device__ __forceinline__ void mma16816(float* c, const uint32_t* a,
                                         uint32_t b0, uint32_t b1) {
    asm volatile(
        "mma.sync.aligned.m16n8k16.row.col.f32.bf16.bf16.f32 "
        "{%0,%1,%2,%3}, {%4,%5,%6,%7}, {%8,%9}, {%0,%1,%2,%3};"
        : "+f"(c[0]), "+f"(c[1]), "+f"(c[2]), "+f"(c[3])
        : "r"(a[0]), "r"(a[1]), "r"(a[2]), "r"(a[3]), "r"(b0), "r"(b1));
}

// ---------------- prep: FsT (bf16 transpose, 32 rows/blk) + sum(F^2) + diag --
__global__ void __launch_bounds__(256, 4)
prep_fst(const float* __restrict__ F, const float* __restrict__ Dv,
         const float* __restrict__ De, int Nn, int Ee) {
    __shared__ __nv_bfloat16 s[32][132];
    __shared__ float red[256];
    __shared__ float dvis[32];
    const int t = threadIdx.x;
    const int n0 = blockIdx.x * 32;

    if (t < 32) {
        int n = n0 + t;
        dvis[t] = (n < Nn) ? rsqrtf(Dv[(size_t)n * Nn + n] + EPSF) : 0.f;
    }
    if (blockIdx.x < 20) {
        int e = blockIdx.x * 256 + t;
        g_deinv[e] = (e < Ee) ? 1.f / (De[(size_t)e * Ee + e] + EPSF) : 0.f;
    }
    __syncthreads();

    float f2 = 0.f;
    #pragma unroll
    for (int i = 0; i < 4; ++i) {
        int g = t + 256 * i;          // 1024 float4 slots (32 n x 32)
        int nl = g >> 5;
        int d4 = (g & 31) * 4;
        int n = n0 + nl;
        float4 v = make_float4(0.f, 0.f, 0.f, 0.f);
        float sc = 0.f;
        if (n < Nn) { v = *(const float4*)&F[(size_t)n * DD + d4]; sc = dvis[nl]; }
        f2 += v.x * v.x + v.y * v.y + v.z * v.z + v.w * v.w;
        s[nl][d4 + 0] = __float2bfloat16(v.x * sc);
        s[nl][d4 + 1] = __float2bfloat16(v.y * sc);
        s[nl][d4 + 2] = __float2bfloat16(v.z * sc);
        s[nl][d4 + 3] = __float2bfloat16(v.w * sc);
    }
    __syncthreads();
    {
        int d = t >> 1;
        int nh = (t & 1) * 16;
        uint32_t w[8];
        #pragma unroll
        for (int j = 0; j < 8; ++j) {
            __nv_bfloat162 p;
            p.x = s[nh + 2 * j][d];
            p.y = s[nh + 2 * j + 1][d];
            w[j] = *(uint32_t*)&p;
        }
        uint4* dst = (uint4*)&g_FsT[(size_t)d * KPAD + n0 + nh];
        dst[0] = make_uint4(w[0], w[1], w[2], w[3]);
        dst[1] = make_uint4(w[4], w[5], w[6], w[7]);
    }
    red[t] = f2;
    __syncthreads();
    #pragma unroll
    for (int s2 = 128; s2 > 0; s2 >>= 1) {
        if (t < s2) red[t] += red[t + s2];
        __syncthreads();
    }
    if (t == 0) g_f2sum[blockIdx.x] = red[0];
}

// ---------------- GEMM + fused tile/final reduce -----------------------------
// CTA tile 128(d) x 128(e), grid (etiles=40, NKS=7).
// Dynamic SMEM 64KB: A 2x16KB @0, B 2x16KB @32768 (lo/hi 8KB).
__global__ void __launch_bounds__(256, 2)
gemm_kernel(const float* __restrict__ H, float* __restrict__ out,
            int Nn, int Ee, int nprep) {
    extern __shared__ __align__(1024) char smem[];
    const uint32_t sb = smem_u32(smem);

    const int t = threadIdx.x;
    const int lane = t & 31;
    const int wid = t >> 5;
    const int wm = wid & 3;            // 4 m-warps
    const int wn = wid >> 2;           // 2 n-warps (64 e each)
    const int m0 = wm * 32;

    const int et = blockIdx.x;
    const int e0 = et * 128;
    const int ks = blockIdx.y;
    const int c0 = (ks * NCHUNKS) / NKS;
    const int c1 = ((ks + 1) * NCHUNKS) / NKS;
    const int nch = c1 - c0;
    const bool tail = (e0 + 128 > Ee);

    const int krow = t >> 2;           // 0..63
    const int ecol = (t & 3) * 32;     // 32 e per thread
    const int eloc = ecol & 63;

    float acc[2][8][4];
    #pragma unroll
    for (int i = 0; i < 2; ++i)
        #pragma unroll
        for (int j = 0; j < 8; ++j)
            #pragma unroll
            for (int q = 0; q < 4; ++q) acc[i][j][q] = 0.f;

    const int aRow = (lane & 15);
    const int aKh  = (lane >> 4) * 8;
    const int bKr  = (lane & 15);
    const int bNc  = (lane >> 4) * 8;

    uint32_t w[16];                    // converted B staging (bf16x2)

#define LOAD_A(buf, chunk) do {                                              \
        int _cg = (chunk);                                                   \
        _Pragma("unroll")                                                    \
        for (int _i = 0; _i < 4; ++_i) {                                     \
            int pos = t + 256 * _i;                                          \
            int row = pos >> 3;                                              \
            int cc  = pos & 7;                                               \
            const __nv_bfloat16* src = &g_FsT[(size_t)row * KPAD + _cg * 64 + cc * 8]; \
            uint32_t off = (uint32_t)(row * 128 + cc * 16);                  \
            CPA16((buf) + SWZ(off), src);                                    \
        }                                                                    \
    } while (0)

#define LDG_H(chunk) do {                                                    \
        int _n = (chunk) * 64 + krow;                                        \
        bool _v = _n < Nn;                                                   \
        const float* _hr = H + (size_t)_n * Ee;                              \
        _Pragma("unroll")                                                    \
        for (int _j = 0; _j < 8; ++_j) {                                     \
            float4 f;                                                        \
            if (!tail) {                                                     \
                f = _v ? __ldcs((const float4*)&_hr[e0 + ecol + 4 * _j])     \
                       : make_float4(0.f, 0.f, 0.f, 0.f);                    \
            } else {                                                         \
                int _e = e0 + ecol + 4 * _j;                                 \
                f.x = (_v && _e + 0 < Ee) ? __ldcs(&_hr[_e + 0]) : 0.f;      \
                f.y = (_v && _e + 1 < Ee) ? __ldcs(&_hr[_e + 1]) : 0.f;      \
                f.z = (_v && _e + 2 < Ee) ? __ldcs(&_hr[_e + 2]) : 0.f;      \
                f.w = (_v && _e + 3 < Ee) ? __ldcs(&_hr[_e + 3]) : 0.f;      \
            }                                                                \
            __nv_bfloat162 p0 = __floats2bfloat162_rn(f.x, f.y);             \
            __nv_bfloat162 p1 = __floats2bfloat162_rn(f.z, f.w);             \
            w[2 * _j]     = *(uint32_t*)&p0;                                 \
            w[2 * _j + 1] = *(uint32_t*)&p1;                                 \
        }                                                                    \
    } while (0)

#define STS_H(bbase) do {                                                    \
        uint32_t reg = (bbase) + ((t & 2) ? 8192u : 0u);                     \
        uint32_t off = (uint32_t)(krow * 128 + eloc * 2);                    \
        sts128(reg + SWZ(off),      w[0],  w[1],  w[2],  w[3]);              \
        sts128(reg + SWZ(off + 16), w[4],  w[5],  w[6],  w[7]);              \
        sts128(reg + SWZ(off + 32), w[8],  w[9],  w[10], w[11]);             \
        sts128(reg + SWZ(off + 48), w[12], w[13], w[14], w[15]);             \
    } while (0)

#define COMPUTE(abuf, bbase) do {                                            \
        uint32_t breg = (bbase) + (wn ? 8192u : 0u);                         \
        _Pragma("unroll")                                                    \
        for (int k0 = 0; k0 < 64; k0 += 16) {                                \
            uint32_t afr[2][4];                                              \
            _Pragma("unroll")                                                \
            for (int i = 0; i < 2; ++i) {                                    \
                uint32_t off = (uint32_t)((m0 + i * 16 + aRow) * 128         \
                                          + (k0 + aKh) * 2);                 \
                LDSM4(afr[i], (abuf) + SWZ(off));                            \
            }                                                                \
            uint32_t bfr[4][4];                                              \
            _Pragma("unroll")                                                \
            for (int jb = 0; jb < 4; ++jb) {                                 \
                uint32_t off = (uint32_t)((k0 + bKr) * 128                   \
                                          + (jb * 16 + bNc) * 2);            \
                LDSM4T(bfr[jb], breg + SWZ(off));                            \
            }                                                                \
            _Pragma("unroll")                                                \
            for (int i = 0; i < 2; ++i)                                      \
                _Pragma("unroll")                                            \
                for (int j = 0; j < 8; ++j)                                  \
                    mma16816(acc[i][j], afr[i],                              \
                             bfr[j >> 1][(j & 1) * 2],                       \
                             bfr[j >> 1][(j & 1) * 2 + 1]);                  \
        }                                                                    \
    } while (0)

    // ---- pipeline (double-buffered) ----
    LOAD_A(sb, c0);
    CPA_COMMIT();
    LDG_H(c0);
    CPA_WAIT0();
    STS_H(sb + 32768);
    __syncthreads();

    for (int cc = 0; cc < nch; ++cc) {
        const int b = cc & 1;
        const uint32_t aCur = sb + b * 16384;
        const uint32_t bCur = sb + 32768 + b * 16384;
        const uint32_t aNxt = sb + (b ^ 1) * 16384;
        const uint32_t bNxt = sb + 32768 + (b ^ 1) * 16384;
        const bool has = (cc + 1) < nch;
        if (has) {
            LOAD_A(aNxt, c0 + cc + 1);
            CPA_COMMIT();
            LDG_H(c0 + cc + 1);
        }
        COMPUTE(aCur, bCur);
        if (has) {
            CPA_WAIT0();
            STS_H(bNxt);
        }
        __syncthreads();
    }

    // ---- write partials: g_Mpart[ks][d][e] ----
    const int wn64 = wn * 64;
    #pragma unroll
    for (int i = 0; i < 2; ++i) {
        #pragma unroll
        for (int j = 0; j < 8; ++j) {
            int d = m0 + i * 16 + (lane >> 2);
            int e = e0 + wn64 + j * 8 + (lane & 3) * 2;
            size_t base = ((size_t)(ks * DD + d)) * EPITCH + e;
            *(float2*)&g_Mpart[base] = make_float2(acc[i][j][0], acc[i][j][1]);
            *(float2*)&g_Mpart[base + (size_t)8 * EPITCH] =
                make_float2(acc[i][j][2], acc[i][j][3]);
        }
    }

    // ---- fused tile reduce: 7th CTA of this e-tile reduces it ----
    __threadfence();
    __syncthreads();
    __shared__ int sLastTile;
    if (t == 0) {
        int c = atomicAdd(&g_tilecnt[et], 1);
        sLastTile = (c == NKS - 1);
        if (sLastTile) g_tilecnt[et] = 0;     // reset for next replay
    }
    __syncthreads();
    if (!sLastTile) return;

    {
        float* r = (float*)smem;
        __threadfence();                       // acquire side
        const int el = t & 127;
        const int dg = t >> 7;                 // 0 or 1 (64 d each)
        const int e = e0 + el;
        float acc2 = 0.f;
        #pragma unroll 4
        for (int d = dg * 64; d < dg * 64 + 64; ++d) {
            float v = 0.f;
            #pragma unroll
            for (int j = 0; j < NKS; ++j)
                v += g_Mpart[((size_t)(j * DD + d)) * EPITCH + e];
            acc2 += v * v;
        }
        r[t] = acc2 * g_deinv[e];
        __syncthreads();
        #pragma unroll
        for (int s = 128; s > 0; s >>= 1) {
            if (t < s) r[t] += r[t + s];
            __syncthreads();
        }
        __shared__ int sLastAll;
        if (t == 0) {
            g_blocksum[et] = r[0];
            __threadfence();
            int dcount = atomicAdd(&g_donecnt, 1);
            sLastAll = (dcount == (int)gridDim.x - 1);
            if (sLastAll) { g_donecnt = 0; __threadfence(); }
        }
        __syncthreads();
        if (!sLastAll) return;

        // ---- final combine (single CTA) ----
        float a2 = 0.f;
        for (int i = t; i < nprep; i += 256) a2 += g_f2sum[i];
        for (int i = t; i < (int)gridDim.x; i += 256) a2 -= g_blocksum[i];
        r[t] = a2;
        __syncthreads();
        #pragma unroll
        for (int s = 128; s > 0; s >>= 1) {
            if (t < s) r[t] += r[t + s];
            __syncthreads();
        }
        if (t == 0) out[0] = r[0] / (float)Nn;
    }
}

// ---------------- launch ------------------------------------------------------
extern "C" void kernel_launch(void* const* d_in, const int* in_sizes, int n_in,
                              void* d_out, int out_size) {
    const float* F  = (const float*)d_in[0];   // [N,128]
    const float* H  = (const float*)d_in[1];   // [N,E]
    const float* Dv = (const float*)d_in[2];   // [N,N]
    const float* De = (const float*)d_in[3];   // [E,E]
    float* out = (float*)d_out;

    int Nn = in_sizes[0] / DD;                 // 10000
    int Ee = in_sizes[1] / Nn;                 // 5000
    int etiles = (Ee + 127) / 128;             // 40
    int nprep = KPAD / 32;                     // 314

    cudaFuncSetAttribute(gemm_kernel, cudaFuncAttributeMaxDynamicSharedMemorySize,
                         65536);

    prep_fst<<<nprep, 256>>>(F, Dv, De, Nn, Ee);
    gemm_kernel<<<dim3(etiles, NKS), 256, 65536>>>(H, out, Nn, Ee, nprep);
}

// round 10
// speedup vs baseline: 1.3946x; 1.3946x over previous
#include <cuda_runtime.h>
#include <cuda_bf16.h>
#include <stdint.h>
#include <math.h>

#define EPSF 1e-8f
#define DD 128               // d
#define KPAD 10048           // 314*32 padded K (= problem N)
#define NCHUNKS 157          // 64-k chunks
#define EPAD 5120
#define EPITCH 5120          // 40*128
#define NKS 7                // K splits

// ---------------- static device scratch (no allocation) ----------------------
static __device__ __align__(256) __nv_bfloat16 g_FsT[DD * KPAD];     // Fs^T K-major bf16
static __device__ __align__(256) float g_Mpart[NKS * DD * EPITCH];   // 18.35 MB partials
static __device__ float g_deinv[EPAD];
static __device__ float g_blocksum[2560];
static __device__ float g_f2sum[320];
static __device__ int   g_count;

// ---------------- helpers ----------------------------------------------------
__device__ __forceinline__ uint32_t smem_u32(const void* p) {
    uint32_t a;
    asm("{ .reg .u64 t; cvta.to.shared.u64 t, %1; cvt.u32.u64 %0, t; }"
        : "=r"(a) : "l"(p));
    return a;
}
#define SWZ(o) ((o) ^ (((o) >> 3) & 0x70))

__device__ __forceinline__ void sts128(uint32_t addr, uint32_t a, uint32_t b,
                                       uint32_t c, uint32_t d) {
    asm volatile("st.shared.v4.b32 [%0], {%1,%2,%3,%4};"
                 :: "r"(addr), "r"(a), "r"(b), "r"(c), "r"(d) : "memory");
}
// cp.async with .cg: bypasses L1 on the global-read side (16B only)
#define CPA16(dst, src) \
    asm volatile("cp.async.cg.shared.global [%0], [%1], 16;" \
                 :: "r"(dst), "l"(src) : "memory")
#define CPA_COMMIT() asm volatile("cp.async.commit_group;" ::: "memory")
#define CPA_WAIT0()  asm volatile("cp.async.wait_group 0;" ::: "memory")

#define LDSM4(r, addr) \
    asm volatile("ldmatrix.sync.aligned.m8n8.x4.shared.b16 {%0,%1,%2,%3}, [%4];" \
                 : "=r"((r)[0]), "=r"((r)[1]), "=r"((r)[2]), "=r"((r)[3]) : "r"(addr))
#define LDSM4T(r, addr) \
    asm volatile("ldmatrix.sync.aligned.m8n8.x4.trans.shared.b16 {%0,%1,%2,%3}, [%4];" \
                 : "=r"((r)[0]), "=r"((r)[1]), "=r"((r)[2]), "=r"((r)[3]) : "r"(addr))

__device__ __forceinline__ void mma16816(float* c, const uint32_t* a,
                                         uint32_t b0, uint32_t b1) {
    asm volatile(
        "mma.sync.aligned.m16n8k16.row.col.f32.bf16.bf16.f32 "
        "{%0,%1,%2,%3}, {%4,%5,%6,%7}, {%8,%9}, {%0,%1,%2,%3};"
        : "+f"(c[0]), "+f"(c[1]), "+f"(c[2]), "+f"(c[3])
        : "r"(a[0]), "r"(a[1]), "r"(a[2]), "r"(a[3]), "r"(b0), "r"(b1));
}

// ---------------- prep: FsT (bf16 transpose, 32 rows/blk) + sum(F^2) + diag --
__global__ void __launch_bounds__(256, 4)
prep_fst(const float* __restrict__ F, const float* __restrict__ Dv,
         const float* __restrict__ De, int Nn, int Ee) {
    __shared__ __nv_bfloat16 s[32][132];
    __shared__ float red[256];
    __shared__ float dvis[32];
    const int t = threadIdx.x;
    const int n0 = blockIdx.x * 32;

    if (t < 32) {
        int n = n0 + t;
        dvis[t] = (n < Nn) ? rsqrtf(Dv[(size_t)n * Nn + n] + EPSF) : 0.f;
    }
    if (blockIdx.x < 20) {
        int e = blockIdx.x * 256 + t;
        g_deinv[e] = (e < Ee) ? 1.f / (De[(size_t)e * Ee + e] + EPSF) : 0.f;
    }
    __syncthreads();

    float f2 = 0.f;
    #pragma unroll
    for (int i = 0; i < 4; ++i) {
        int g = t + 256 * i;          // 1024 float4 slots (32 n x 32)
        int nl = g >> 5;
        int d4 = (g & 31) * 4;
        int n = n0 + nl;
        float4 v = make_float4(0.f, 0.f, 0.f, 0.f);
        float sc = 0.f;
        if (n < Nn) { v = *(const float4*)&F[(size_t)n * DD + d4]; sc = dvis[nl]; }
        f2 += v.x * v.x + v.y * v.y + v.z * v.z + v.w * v.w;
        s[nl][d4 + 0] = __float2bfloat16(v.x * sc);
        s[nl][d4 + 1] = __float2bfloat16(v.y * sc);
        s[nl][d4 + 2] = __float2bfloat16(v.z * sc);
        s[nl][d4 + 3] = __float2bfloat16(v.w * sc);
    }
    __syncthreads();
    {
        int d = t >> 1;
        int nh = (t & 1) * 16;
        uint32_t w[8];
        #pragma unroll
        for (int j = 0; j < 8; ++j) {
            __nv_bfloat162 p;
            p.x = s[nh + 2 * j][d];
            p.y = s[nh + 2 * j + 1][d];
            w[j] = *(uint32_t*)&p;
        }
        uint4* dst = (uint4*)&g_FsT[(size_t)d * KPAD + n0 + nh];
        dst[0] = make_uint4(w[0], w[1], w[2], w[3]);
        dst[1] = make_uint4(w[4], w[5], w[6], w[7]);
    }
    red[t] = f2;
    __syncthreads();
    #pragma unroll
    for (int s2 = 128; s2 > 0; s2 >>= 1) {
        if (t < s2) red[t] += red[t + s2];
        __syncthreads();
    }
    if (t == 0) g_f2sum[blockIdx.x] = red[0];
}

// ---------------- GEMM: mma.sync bf16, CTA tile 128(d) x 128(e), K-split -----
// Dynamic SMEM 64KB: A 2x16KB @0, B 2x16KB @32768 (lo/hi 8KB).
__global__ void __launch_bounds__(256, 2)
gemm_kernel(const float* __restrict__ H, int Nn, int Ee) {
    extern __shared__ __align__(1024) char smem[];
    const uint32_t sb = smem_u32(smem);

    const int t = threadIdx.x;
    const int lane = t & 31;
    const int wid = t >> 5;
    const int wm = wid & 3;            // 4 m-warps
    const int wn = wid >> 2;           // 2 n-warps (64 e each)
    const int m0 = wm * 32;

    const int e0 = blockIdx.x * 128;
    const int ks = blockIdx.y;
    const int c0 = (ks * NCHUNKS) / NKS;
    const int c1 = ((ks + 1) * NCHUNKS) / NKS;
    const int nch = c1 - c0;
    const bool tail = (e0 + 128 > Ee);

    const int krow = t >> 2;           // 0..63
    const int ecol = (t & 3) * 32;     // 32 e per thread
    const int eloc = ecol & 63;

    float acc[2][8][4];
    #pragma unroll
    for (int i = 0; i < 2; ++i)
        #pragma unroll
        for (int j = 0; j < 8; ++j)
            #pragma unroll
            for (int q = 0; q < 4; ++q) acc[i][j][q] = 0.f;

    const int aRow = (lane & 15);
    const int aKh  = (lane >> 4) * 8;
    const int bKr  = (lane & 15);
    const int bNc  = (lane >> 4) * 8;

    uint32_t w[16];                    // converted B staging (bf16x2)

#define LOAD_A(buf, chunk) do {                                              \
        int _cg = (chunk);                                                   \
        _Pragma("unroll")                                                    \
        for (int _i = 0; _i < 4; ++_i) {                                     \
            int pos = t + 256 * _i;                                          \
            int row = pos >> 3;                                              \
            int cc  = pos & 7;                                               \
            const __nv_bfloat16* src = &g_FsT[(size_t)row * KPAD + _cg * 64 + cc * 8]; \
            uint32_t off = (uint32_t)(row * 128 + cc * 16);                  \
            CPA16((buf) + SWZ(off), src);                                    \
        }                                                                    \
    } while (0)

#define LDG_H(chunk) do {                                                    \
        int _n = (chunk) * 64 + krow;                                        \
        bool _v = _n < Nn;                                                   \
        const float* _hr = H + (size_t)_n * Ee;                              \
        _Pragma("unroll")                                                    \
        for (int _j = 0; _j < 8; ++_j) {                                     \
            float4 f;                                                        \
            if (!tail) {                                                     \
                f = _v ? __ldcg((const float4*)&_hr[e0 + ecol + 4 * _j])     \
                       : make_float4(0.f, 0.f, 0.f, 0.f);                    \
            } else {                                                         \
                int _e = e0 + ecol + 4 * _j;                                 \
                f.x = (_v && _e + 0 < Ee) ? __ldcg(&_hr[_e + 0]) : 0.f;      \
                f.y = (_v && _e + 1 < Ee) ? __ldcg(&_hr[_e + 1]) : 0.f;      \
                f.z = (_v && _e + 2 < Ee) ? __ldcg(&_hr[_e + 2]) : 0.f;      \
                f.w = (_v && _e + 3 < Ee) ? __ldcg(&_hr[_e + 3]) : 0.f;      \
            }                                                                \
            __nv_bfloat162 p0 = __floats2bfloat162_rn(f.x, f.y);             \
            __nv_bfloat162 p1 = __floats2bfloat162_rn(f.z, f.w);             \
            w[2 * _j]     = *(uint32_t*)&p0;                                 \
            w[2 * _j + 1] = *(uint32_t*)&p1;                                 \
        }                                                                    \
    } while (0)

#define STS_H(bbase) do {                                                    \
        uint32_t reg = (bbase) + ((t & 2) ? 8192u : 0u);                     \
        uint32_t off = (uint32_t)(krow * 128 + eloc * 2);                    \
        sts128(reg + SWZ(off),      w[0],  w[1],  w[2],  w[3]);              \
        sts128(reg + SWZ(off + 16), w[4],  w[5],  w[6],  w[7]);              \
        sts128(reg + SWZ(off + 32), w[8],  w[9],  w[10], w[11]);             \
        sts128(reg + SWZ(off + 48), w[12], w[13], w[14], w[15]);             \
    } while (0)

#define COMPUTE(abuf, bbase) do {                                            \
        uint32_t breg = (bbase) + (wn ? 8192u : 0u);                         \
        _Pragma("unroll")                                                    \
        for (int k0 = 0; k0 < 64; k0 += 16) {                                \
            uint32_t afr[2][4];                                              \
            _Pragma("unroll")                                                \
            for (int i = 0; i < 2; ++i) {                                    \
                uint32_t off = (uint32_t)((m0 + i * 16 + aRow) * 128         \
                                          + (k0 + aKh) * 2);                 \
                LDSM4(afr[i], (abuf) + SWZ(off));                            \
            }                                                                \
            uint32_t bfr[4][4];                                              \
            _Pragma("unroll")                                                \
            for (int jb = 0; jb < 4; ++jb) {                                 \
                uint32_t off = (uint32_t)((k0 + bKr) * 128                   \
                                          + (jb * 16 + bNc) * 2);            \
                LDSM4T(bfr[jb], breg + SWZ(off));                            \
            }                                                                \
            _Pragma("unroll")                                                \
            for (int i = 0; i < 2; ++i)                                      \
                _Pragma("unroll")                                            \
                for (int j = 0; j < 8; ++j)                                  \
                    mma16816(acc[i][j], afr[i],                              \
                             bfr[j >> 1][(j & 1) * 2],                       \
                             bfr[j >> 1][(j & 1) * 2 + 1]);                  \
        }                                                                    \
    } while (0)

    // ---- pipeline (double-buffered) ----
    LOAD_A(sb, c0);
    CPA_COMMIT();
    LDG_H(c0);
    CPA_WAIT0();
    STS_H(sb + 32768);
    __syncthreads();

    for (int cc = 0; cc < nch; ++cc) {
        const int b = cc & 1;
        const uint32_t aCur = sb + b * 16384;
        const uint32_t bCur = sb + 32768 + b * 16384;
        const uint32_t aNxt = sb + (b ^ 1) * 16384;
        const uint32_t bNxt = sb + 32768 + (b ^ 1) * 16384;
        const bool has = (cc + 1) < nch;
        if (has) {
            LOAD_A(aNxt, c0 + cc + 1);
            CPA_COMMIT();
            LDG_H(c0 + cc + 1);
        }
        COMPUTE(aCur, bCur);
        if (has) {
            CPA_WAIT0();
            STS_H(bNxt);
        }
        __syncthreads();
    }

    // ---- write partials: g_Mpart[ks][d][e] ----
    const int wn64 = wn * 64;
    #pragma unroll
    for (int i = 0; i < 2; ++i) {
        #pragma unroll
        for (int j = 0; j < 8; ++j) {
            int d = m0 + i * 16 + (lane >> 2);
            int e = e0 + wn64 + j * 8 + (lane & 3) * 2;
            size_t base = ((size_t)(ks * DD + d)) * EPITCH + e;
            *(float2*)&g_Mpart[base] = make_float2(acc[i][j][0], acc[i][j][1]);
            *(float2*)&g_Mpart[base + (size_t)8 * EPITCH] =
                make_float2(acc[i][j][2], acc[i][j][3]);
        }
    }
}

// ---------------- pass 3 + fused final reduce --------------------------------
// grid 2560: d = bid/20, e = (bid%20)*256 + t. Last block does the final sum.
__global__ void __launch_bounds__(256, 8)
pass3_kernel(float* __restrict__ out, int Nn, int nprep) {
    __shared__ float r[256];
    __shared__ int isLast;
    const int t = threadIdx.x;
    const int d = blockIdx.x / 20;
    const int e = (blockIdx.x % 20) * 256 + t;
    float v = 0.f;
    #pragma unroll
    for (int j = 0; j < NKS; ++j)
        v += g_Mpart[((size_t)(j * DD + d)) * EPITCH + e];
    r[t] = v * v * g_deinv[e];
    __syncthreads();
    #pragma unroll
    for (int s = 128; s > 0; s >>= 1) {
        if (t < s) r[t] += r[t + s];
        __syncthreads();
    }
    if (t == 0) {
        g_blocksum[blockIdx.x] = r[0];
        __threadfence();
        int done = atomicAdd(&g_count, 1);
        isLast = (done == (int)gridDim.x - 1);
    }
    __syncthreads();
    if (isLast) {
        float acc = 0.f;
        for (int i = t; i < nprep; i += 256) acc += g_f2sum[i];
        for (int i = t; i < 2560; i += 256) acc -= g_blocksum[i];
        r[t] = acc;
        __syncthreads();
        #pragma unroll
        for (int s = 128; s > 0; s >>= 1) {
            if (t < s) r[t] += r[t + s];
            __syncthreads();
        }
        if (t == 0) {
            out[0] = r[0] / (float)Nn;
            g_count = 0;               // reset for next graph replay
        }
    }
}

// ---------------- launch ------------------------------------------------------
extern "C" void kernel_launch(void* const* d_in, const int* in_sizes, int n_in,
                              void* d_out, int out_size) {
    const float* F  = (const float*)d_in[0];   // [N,128]
    const float* H  = (const float*)d_in[1];   // [N,E]
    const float* Dv = (const float*)d_in[2];   // [N,N]
    const float* De = (const float*)d_in[3];   // [E,E]
    float* out = (float*)d_out;

    int Nn = in_sizes[0] / DD;                 // 10000
    int Ee = in_sizes[1] / Nn;                 // 5000
    int etiles = (Ee + 127) / 128;             // 40
    int nprep = KPAD / 32;                     // 314

    cudaFuncSetAttribute(gemm_kernel, cudaFuncAttributeMaxDynamicSharedMemorySize,
                         65536);

    prep_fst<<<nprep, 256>>>(F, Dv, De, Nn, Ee);
    gemm_kernel<<<dim3(etiles, NKS), 256, 65536>>>(H, Nn, Ee);
    pass3_kernel<<<2560, 256>>>(out, Nn, nprep);
}

// round 11
// speedup vs baseline: 1.6051x; 1.1510x over previous
#include <cuda_runtime.h>
#include <cuda_bf16.h>
#include <stdint.h>
#include <math.h>

#define EPSF 1e-8f
#define DD 128               // d
#define KPAD 10048           // 314*32 padded K (= problem N)
#define NCHUNKS 157          // 64-k chunks
#define EPAD 5120
#define EPITCH 5120
#define NSL 6                // max K slices

// ---------------- static device scratch (no allocation) ----------------------
static __device__ __align__(256) __nv_bfloat16 g_FsT[DD * KPAD];     // Fs^T K-major bf16
static __device__ __align__(256) float g_Mpart[NSL * DD * EPITCH];   // 15.7 MB (zero-init)
static __device__ float g_deinv[EPAD];
static __device__ float g_blocksum[2560];
static __device__ float g_f2sum[320];
static __device__ int   g_count;

// ---------------- helpers ----------------------------------------------------
__device__ __forceinline__ uint32_t smem_u32(const void* p) {
    uint32_t a;
    asm("{ .reg .u64 t; cvta.to.shared.u64 t, %1; cvt.u32.u64 %0, t; }"
        : "=r"(a) : "l"(p));
    return a;
}
#define SWZ(o) ((o) ^ (((o) >> 3) & 0x70))

__device__ __forceinline__ void sts128(uint32_t addr, uint32_t a, uint32_t b,
                                       uint32_t c, uint32_t d) {
    asm volatile("st.shared.v4.b32 [%0], {%1,%2,%3,%4};"
                 :: "r"(addr), "r"(a), "r"(b), "r"(c), "r"(d) : "memory");
}
#define CPA16(dst, src) \
    asm volatile("cp.async.cg.shared.global [%0], [%1], 16;" \
                 :: "r"(dst), "l"(src) : "memory")
#define CPA_COMMIT() asm volatile("cp.async.commit_group;" ::: "memory")
#define CPA_WAIT0()  asm volatile("cp.async.wait_group 0;" ::: "memory")

#define LDSM4(r, addr) \
    asm volatile("ldmatrix.sync.aligned.m8n8.x4.shared.b16 {%0,%1,%2,%3}, [%4];" \
                 : "=r"((r)[0]), "=r"((r)[1]), "=r"((r)[2]), "=r"((r)[3]) : "r"(addr))
#define LDSM4T(r, addr) \
    asm volatile("ldmatrix.sync.aligned.m8n8.x4.trans.shared.b16 {%0,%1,%2,%3}, [%4];" \
                 : "=r"((r)[0]), "=r"((r)[1]), "=r"((r)[2]), "=r"((r)[3]) : "r"(addr))

__device__ __forceinline__ void mma16816(float* c, const uint32_t* a,
                                         uint32_t b0, uint32_t b1) {
    asm volatile(
        "mma.sync.aligned.m16n8k16.row.col.f32.bf16.bf16.f32 "
        "{%0,%1,%2,%3}, {%4,%5,%6,%7}, {%8,%9}, {%0,%1,%2,%3};"
        : "+f"(c[0]), "+f"(c[1]), "+f"(c[2]), "+f"(c[3])
        : "r"(a[0]), "r"(a[1]), "r"(a[2]), "r"(a[3]), "r"(b0), "r"(b1));
}

// ---------------- prep: FsT (bf16 transpose, 32 rows/blk) + sum(F^2) + diag --
__global__ void __launch_bounds__(256, 4)
prep_fst(const float* __restrict__ F, const float* __restrict__ Dv,
         const float* __restrict__ De, int Nn, int Ee) {
    __shared__ __nv_bfloat16 s[32][132];
    __shared__ float red[256];
    __shared__ float dvis[32];
    const int t = threadIdx.x;
    const int n0 = blockIdx.x * 32;

    if (t < 32) {
        int n = n0 + t;
        dvis[t] = (n < Nn) ? rsqrtf(Dv[(size_t)n * Nn + n] + EPSF) : 0.f;
    }
    if (blockIdx.x < 20) {
        int e = blockIdx.x * 256 + t;
        g_deinv[e] = (e < Ee) ? 1.f / (De[(size_t)e * Ee + e] + EPSF) : 0.f;
    }
    __syncthreads();

    float f2 = 0.f;
    #pragma unroll
    for (int i = 0; i < 4; ++i) {
        int g = t + 256 * i;          // 1024 float4 slots (32 n x 32)
        int nl = g >> 5;
        int d4 = (g & 31) * 4;
        int n = n0 + nl;
        float4 v = make_float4(0.f, 0.f, 0.f, 0.f);
        float sc = 0.f;
        if (n < Nn) { v = *(const float4*)&F[(size_t)n * DD + d4]; sc = dvis[nl]; }
        f2 += v.x * v.x + v.y * v.y + v.z * v.z + v.w * v.w;
        s[nl][d4 + 0] = __float2bfloat16(v.x * sc);
        s[nl][d4 + 1] = __float2bfloat16(v.y * sc);
        s[nl][d4 + 2] = __float2bfloat16(v.z * sc);
        s[nl][d4 + 3] = __float2bfloat16(v.w * sc);
    }
    __syncthreads();
    {
        int d = t >> 1;
        int nh = (t & 1) * 16;
        uint32_t w[8];
        #pragma unroll
        for (int j = 0; j < 8; ++j) {
            __nv_bfloat162 p;
            p.x = s[nh + 2 * j][d];
            p.y = s[nh + 2 * j + 1][d];
            w[j] = *(uint32_t*)&p;
        }
        uint4* dst = (uint4*)&g_FsT[(size_t)d * KPAD + n0 + nh];
        dst[0] = make_uint4(w[0], w[1], w[2], w[3]);
        dst[1] = make_uint4(w[4], w[5], w[6], w[7]);
    }
    red[t] = f2;
    __syncthreads();
    #pragma unroll
    for (int s2 = 128; s2 > 0; s2 >>= 1) {
        if (t < s2) red[t] += red[t + s2];
        __syncthreads();
    }
    if (t == 0) g_f2sum[blockIdx.x] = red[0];
}

// ---------------- GEMM: mma.sync bf16, CTA tile 128(d) x 64(e), occ 3 --------
// Grid 444 = 49 e-tiles x 6 slices + 30 e-tiles x 5 slices (one wave at occ 3)
// Dynamic SMEM 48KB: A 2x16KB @0, B 2x8KB @32768.
__global__ void __launch_bounds__(256, 3)
gemm_kernel(const float* __restrict__ H, int Nn, int Ee) {
    extern __shared__ __align__(1024) char smem[];
    const uint32_t sb = smem_u32(smem);

    const int t = threadIdx.x;
    const int lane = t & 31;
    const int wid = t >> 5;
    const int wm = wid & 3;            // 4 m-warps (32 d each)
    const int wn = wid >> 2;           // 2 n-warps (32 e each)
    const int m0 = wm * 32;
    const int n0w = wn * 32;

    // ---- work mapping: 444 CTAs ----
    const int bid = blockIdx.x;
    int et, sl, nsl;
    if (bid < 294) { et = bid / 6;            sl = bid % 6; nsl = 6; }
    else           { int r = bid - 294; et = 49 + r / 5; sl = r % 5; nsl = 5; }
    const int e0 = et * 64;
    const int c0 = (sl * NCHUNKS) / nsl;
    const int c1 = ((sl + 1) * NCHUNKS) / nsl;
    const int nch = c1 - c0;
    const bool tail = (e0 + 64 > Ee);

    const int krow = t >> 2;           // 0..63
    const int ecol = (t & 3) * 16;     // 16 e per thread

    float acc[2][4][4];
    #pragma unroll
    for (int i = 0; i < 2; ++i)
        #pragma unroll
        for (int j = 0; j < 4; ++j)
            #pragma unroll
            for (int q = 0; q < 4; ++q) acc[i][j][q] = 0.f;

    const int aRow = (lane & 15);
    const int aKh  = (lane >> 4) * 8;
    const int bKr  = (lane & 15);
    const int bNc  = (lane >> 4) * 8;

    uint32_t w[8];                     // converted B staging (bf16x2)

#define LOAD_A(buf, chunk) do {                                              \
        int _cg = (chunk);                                                   \
        _Pragma("unroll")                                                    \
        for (int _i = 0; _i < 4; ++_i) {                                     \
            int pos = t + 256 * _i;                                          \
            int row = pos >> 3;                                              \
            int cc  = pos & 7;                                               \
            const __nv_bfloat16* src = &g_FsT[(size_t)row * KPAD + _cg * 64 + cc * 8]; \
            uint32_t off = (uint32_t)(row * 128 + cc * 16);                  \
            CPA16((buf) + SWZ(off), src);                                    \
        }                                                                    \
    } while (0)

#define LDG_H(chunk) do {                                                    \
        int _n = (chunk) * 64 + krow;                                        \
        bool _v = _n < Nn;                                                   \
        const float* _hr = H + (size_t)_n * Ee;                              \
        _Pragma("unroll")                                                    \
        for (int _j = 0; _j < 4; ++_j) {                                     \
            float4 f;                                                        \
            if (!tail) {                                                     \
                f = _v ? __ldcg((const float4*)&_hr[e0 + ecol + 4 * _j])     \
                       : make_float4(0.f, 0.f, 0.f, 0.f);                    \
            } else {                                                         \
                int _e = e0 + ecol + 4 * _j;                                 \
                f.x = (_v && _e + 0 < Ee) ? __ldcg(&_hr[_e + 0]) : 0.f;      \
                f.y = (_v && _e + 1 < Ee) ? __ldcg(&_hr[_e + 1]) : 0.f;      \
                f.z = (_v && _e + 2 < Ee) ? __ldcg(&_hr[_e + 2]) : 0.f;      \
                f.w = (_v && _e + 3 < Ee) ? __ldcg(&_hr[_e + 3]) : 0.f;      \
            }                                                                \
            __nv_bfloat162 p0 = __floats2bfloat162_rn(f.x, f.y);             \
            __nv_bfloat162 p1 = __floats2bfloat162_rn(f.z, f.w);             \
            w[2 * _j]     = *(uint32_t*)&p0;                                 \
            w[2 * _j + 1] = *(uint32_t*)&p1;                                 \
        }                                                                    \
    } while (0)

#define STS_H(buf) do {                                                      \
        uint32_t off = (uint32_t)(krow * 128 + ecol * 2);                    \
        sts128((buf) + SWZ(off),      w[0], w[1], w[2], w[3]);               \
        sts128((buf) + SWZ(off + 16), w[4], w[5], w[6], w[7]);               \
    } while (0)

#define COMPUTE(abuf, bbuf) do {                                             \
        _Pragma("unroll")                                                    \
        for (int k0 = 0; k0 < 64; k0 += 16) {                                \
            uint32_t afr[2][4];                                              \
            _Pragma("unroll")                                                \
            for (int i = 0; i < 2; ++i) {                                    \
                uint32_t off = (uint32_t)((m0 + i * 16 + aRow) * 128         \
                                          + (k0 + aKh) * 2);                 \
                LDSM4(afr[i], (abuf) + SWZ(off));                            \
            }                                                                \
            uint32_t bfr[2][4];                                              \
            _Pragma("unroll")                                                \
            for (int jb = 0; jb < 2; ++jb) {                                 \
                uint32_t off = (uint32_t)((k0 + bKr) * 128                   \
                                          + (n0w + jb * 16 + bNc) * 2);      \
                LDSM4T(bfr[jb], (bbuf) + SWZ(off));                          \
            }                                                                \
            _Pragma("unroll")                                                \
            for (int i = 0; i < 2; ++i)                                      \
                _Pragma("unroll")                                            \
                for (int j = 0; j < 4; ++j)                                  \
                    mma16816(acc[i][j], afr[i],                              \
                             bfr[j >> 1][(j & 1) * 2],                       \
                             bfr[j >> 1][(j & 1) * 2 + 1]);                  \
        }                                                                    \
    } while (0)

    // ---- pipeline (double-buffered) ----
    LOAD_A(sb, c0);
    CPA_COMMIT();
    LDG_H(c0);
    CPA_WAIT0();
    STS_H(sb + 32768);
    __syncthreads();

    for (int cc = 0; cc < nch; ++cc) {
        const int b = cc & 1;
        const uint32_t aCur = sb + b * 16384;
        const uint32_t bCur = sb + 32768 + b * 8192;
        const uint32_t aNxt = sb + (b ^ 1) * 16384;
        const uint32_t bNxt = sb + 32768 + (b ^ 1) * 8192;
        const bool has = (cc + 1) < nch;
        if (has) {
            LOAD_A(aNxt, c0 + cc + 1);
            CPA_COMMIT();
            LDG_H(c0 + cc + 1);
        }
        COMPUTE(aCur, bCur);
        if (has) {
            CPA_WAIT0();
            STS_H(bNxt);
        }
        __syncthreads();
    }

    // ---- write partials: g_Mpart[sl][d][e] ----
    #pragma unroll
    for (int i = 0; i < 2; ++i) {
        #pragma unroll
        for (int j = 0; j < 4; ++j) {
            int d = m0 + i * 16 + (lane >> 2);
            int e = e0 + n0w + j * 8 + (lane & 3) * 2;
            size_t base = ((size_t)(sl * DD + d)) * EPITCH + e;
            *(float2*)&g_Mpart[base] = make_float2(acc[i][j][0], acc[i][j][1]);
            *(float2*)&g_Mpart[base + (size_t)8 * EPITCH] =
                make_float2(acc[i][j][2], acc[i][j][3]);
        }
    }
}

// ---------------- pass 3 + fused final reduce --------------------------------
// grid 2560: d = bid/20, e = (bid%20)*256 + t. Unwritten slices are 0.
__global__ void __launch_bounds__(256, 8)
pass3_kernel(float* __restrict__ out, int Nn, int nprep) {
    __shared__ float r[256];
    __shared__ int isLast;
    const int t = threadIdx.x;
    const int d = blockIdx.x / 20;
    const int e = (blockIdx.x % 20) * 256 + t;
    float v = 0.f;
    #pragma unroll
    for (int j = 0; j < NSL; ++j)
        v += g_Mpart[((size_t)(j * DD + d)) * EPITCH + e];
    r[t] = v * v * g_deinv[e];
    __syncthreads();
    #pragma unroll
    for (int s = 128; s > 0; s >>= 1) {
        if (t < s) r[t] += r[t + s];
        __syncthreads();
    }
    if (t == 0) {
        g_blocksum[blockIdx.x] = r[0];
        __threadfence();
        int done = atomicAdd(&g_count, 1);
        isLast = (done == (int)gridDim.x - 1);
    }
    __syncthreads();
    if (isLast) {
        float acc = 0.f;
        for (int i = t; i < nprep; i += 256) acc += g_f2sum[i];
        for (int i = t; i < 2560; i += 256) acc -= g_blocksum[i];
        r[t] = acc;
        __syncthreads();
        #pragma unroll
        for (int s = 128; s > 0; s >>= 1) {
            if (t < s) r[t] += r[t + s];
            __syncthreads();
        }
        if (t == 0) {
            out[0] = r[0] / (float)Nn;
            g_count = 0;               // reset for next graph replay
        }
    }
}

// ---------------- launch ------------------------------------------------------
extern "C" void kernel_launch(void* const* d_in, const int* in_sizes, int n_in,
                              void* d_out, int out_size) {
    const float* F  = (const float*)d_in[0];   // [N,128]
    const float* H  = (const float*)d_in[1];   // [N,E]
    const float* Dv = (const float*)d_in[2];   // [N,N]
    const float* De = (const float*)d_in[3];   // [E,E]
    float* out = (float*)d_out;

    int Nn = in_sizes[0] / DD;                 // 10000
    int Ee = in_sizes[1] / Nn;                 // 5000
    int nprep = KPAD / 32;                     // 314

    cudaFuncSetAttribute(gemm_kernel, cudaFuncAttributeMaxDynamicSharedMemorySize,
                         49152);

    prep_fst<<<nprep, 256>>>(F, Dv, De, Nn, Ee);
    gemm_kernel<<<444, 256, 49152>>>(H, Nn, Ee);
    pass3_kernel<<<2560, 256>>>(out, Nn, nprep);
}

// round 12
// speedup vs baseline: 1.6218x; 1.0104x over previous
#include <cuda_runtime.h>
#include <cuda_bf16.h>
#include <stdint.h>
#include <math.h>

#define EPSF 1e-8f
#define DD 128               // d
#define KPAD 10048           // 314*32 padded K (= problem N)
#define NCHUNKS 157          // 64-k chunks
#define EPAD 5120
#define EPITCH 5120
#define NSL 6                // max K slices
#define NPREP 314

// ---------------- static device scratch (no allocation) ----------------------
static __device__ __align__(256) __nv_bfloat16 g_FsT[DD * KPAD];     // Fs^T K-major bf16
static __device__ __align__(256) float g_Mpart[NSL * DD * EPITCH];   // 15.7 MB (zero-init)
static __device__ float g_deinv[EPAD];
static __device__ float g_blocksum[2560];
static __device__ float g_f2sum[NPREP + 2];
static __device__ int   g_count;
static __device__ int   g_prepdone;

// ---------------- helpers ----------------------------------------------------
__device__ __forceinline__ uint32_t smem_u32(const void* p) {
    uint32_t a;
    asm("{ .reg .u64 t; cvta.to.shared.u64 t, %1; cvt.u32.u64 %0, t; }"
        : "=r"(a) : "l"(p));
    return a;
}
#define SWZ(o) ((o) ^ (((o) >> 3) & 0x70))

__device__ __forceinline__ void sts128(uint32_t addr, uint32_t a, uint32_t b,
                                       uint32_t c, uint32_t d) {
    asm volatile("st.shared.v4.b32 [%0], {%1,%2,%3,%4};"
                 :: "r"(addr), "r"(a), "r"(b), "r"(c), "r"(d) : "memory");
}
#define CPA16(dst, src) \
    asm volatile("cp.async.cg.shared.global [%0], [%1], 16;" \
                 :: "r"(dst), "l"(src) : "memory")
#define CPA_COMMIT() asm volatile("cp.async.commit_group;" ::: "memory")
#define CPA_WAIT0()  asm volatile("cp.async.wait_group 0;" ::: "memory")

#define LDSM4(r, addr) \
    asm volatile("ldmatrix.sync.aligned.m8n8.x4.shared.b16 {%0,%1,%2,%3}, [%4];" \
                 : "=r"((r)[0]), "=r"((r)[1]), "=r"((r)[2]), "=r"((r)[3]) : "r"(addr))
#define LDSM4T(r, addr) \
    asm volatile("ldmatrix.sync.aligned.m8n8.x4.trans.shared.b16 {%0,%1,%2,%3}, [%4];" \
                 : "=r"((r)[0]), "=r"((r)[1]), "=r"((r)[2]), "=r"((r)[3]) : "r"(addr))

__device__ __forceinline__ void mma16816(float* c, const uint32_t* a,
                                         uint32_t b0, uint32_t b1) {
    asm volatile(
        "mma.sync.aligned.m16n8k16.row.col.f32.bf16.bf16.f32 "
        "{%0,%1,%2,%3}, {%4,%5,%6,%7}, {%8,%9}, {%0,%1,%2,%3};"
        : "+f"(c[0]), "+f"(c[1]), "+f"(c[2]), "+f"(c[3])
        : "r"(a[0]), "r"(a[1]), "r"(a[2]), "r"(a[3]), "r"(b0), "r"(b1));
}

// ---------------- GEMM with fused prep phase ---------------------------------
// Grid 444 = one wave at occ 3. CTAs 0..313: transpose unit; 314..333: deinv.
// Dynamic SMEM 48KB: A 2x16KB @0, B 2x8KB @32768 (prep reuses region 0..~11KB).
__global__ void __launch_bounds__(256, 3)
gemm_kernel(const float* __restrict__ H, const float* __restrict__ F,
            const float* __restrict__ Dv, const float* __restrict__ De,
            int Nn, int Ee) {
    extern __shared__ __align__(1024) char smem[];
    const uint32_t sb = smem_u32(smem);
    const int t = threadIdx.x;
    const int bid = blockIdx.x;

    // ================= phase 1: fused prep =================
    {
        __nv_bfloat16 (*s)[132] = (__nv_bfloat16(*)[132])smem;        // 8448 B
        float* red  = (float*)(smem + 9216);                          // 1024 B
        float* dvis = (float*)(smem + 10240);                         // 128 B
        if (bid < NPREP) {
            const int n0 = bid * 32;
            if (t < 32) {
                int n = n0 + t;
                dvis[t] = (n < Nn) ? rsqrtf(Dv[(size_t)n * Nn + n] + EPSF) : 0.f;
            }
            __syncthreads();
            float f2 = 0.f;
            #pragma unroll
            for (int i = 0; i < 4; ++i) {
                int g = t + 256 * i;
                int nl = g >> 5;
                int d4 = (g & 31) * 4;
                int n = n0 + nl;
                float4 v = make_float4(0.f, 0.f, 0.f, 0.f);
                float sc = 0.f;
                if (n < Nn) { v = *(const float4*)&F[(size_t)n * DD + d4]; sc = dvis[nl]; }
                f2 += v.x * v.x + v.y * v.y + v.z * v.z + v.w * v.w;
                s[nl][d4 + 0] = __float2bfloat16(v.x * sc);
                s[nl][d4 + 1] = __float2bfloat16(v.y * sc);
                s[nl][d4 + 2] = __float2bfloat16(v.z * sc);
                s[nl][d4 + 3] = __float2bfloat16(v.w * sc);
            }
            __syncthreads();
            {
                int d = t >> 1;
                int nh = (t & 1) * 16;
                uint32_t w2[8];
                #pragma unroll
                for (int j = 0; j < 8; ++j) {
                    __nv_bfloat162 p;
                    p.x = s[nh + 2 * j][d];
                    p.y = s[nh + 2 * j + 1][d];
                    w2[j] = *(uint32_t*)&p;
                }
                uint4* dst = (uint4*)&g_FsT[(size_t)d * KPAD + n0 + nh];
                dst[0] = make_uint4(w2[0], w2[1], w2[2], w2[3]);
                dst[1] = make_uint4(w2[4], w2[5], w2[6], w2[7]);
            }
            red[t] = f2;
            __syncthreads();
            #pragma unroll
            for (int s2 = 128; s2 > 0; s2 >>= 1) {
                if (t < s2) red[t] += red[t + s2];
                __syncthreads();
            }
            if (t == 0) {
                g_f2sum[bid] = red[0];
                __threadfence();
                atomicAdd(&g_prepdone, 1);
            }
        } else if (bid < NPREP + 20) {
            int e = (bid - NPREP) * 256 + t;
            if (e < EPAD)
                g_deinv[e] = (e < Ee) ? 1.f / (De[(size_t)e * Ee + e] + EPSF) : 0.f;
        }
        // global spin barrier: all 444 CTAs resident -> safe
        if (t == 0) {
            while (atomicAdd(&g_prepdone, 0) < NPREP) {}
        }
        __syncthreads();
        __threadfence();
    }

    // ================= phase 2: gemm =================
    const int lane = t & 31;
    const int wid = t >> 5;
    const int wm = wid & 3;            // 4 m-warps (32 d each)
    const int wn = wid >> 2;           // 2 n-warps (32 e each)
    const int m0 = wm * 32;
    const int n0w = wn * 32;

    int et, sl, nsl;
    if (bid < 294) { et = bid / 6;            sl = bid % 6; nsl = 6; }
    else           { int r = bid - 294; et = 49 + r / 5; sl = r % 5; nsl = 5; }
    const int e0 = et * 64;
    const int c0 = (sl * NCHUNKS) / nsl;
    const int c1 = ((sl + 1) * NCHUNKS) / nsl;
    const int nch = c1 - c0;
    const bool tail = (e0 + 64 > Ee);

    const int krow = t >> 2;           // 0..63
    const int ecol = (t & 3) * 16;     // 16 e per thread

    float acc[2][4][4];
    #pragma unroll
    for (int i = 0; i < 2; ++i)
        #pragma unroll
        for (int j = 0; j < 4; ++j)
            #pragma unroll
            for (int q = 0; q < 4; ++q) acc[i][j][q] = 0.f;

    const int aRow = (lane & 15);
    const int aKh  = (lane >> 4) * 8;
    const int bKr  = (lane & 15);
    const int bNc  = (lane >> 4) * 8;

    uint32_t w[8];                     // converted B staging (bf16x2)

#define LOAD_A(buf, chunk) do {                                              \
        int _cg = (chunk);                                                   \
        _Pragma("unroll")                                                    \
        for (int _i = 0; _i < 4; ++_i) {                                     \
            int pos = t + 256 * _i;                                          \
            int row = pos >> 3;                                              \
            int cc  = pos & 7;                                               \
            const __nv_bfloat16* src = &g_FsT[(size_t)row * KPAD + _cg * 64 + cc * 8]; \
            uint32_t off = (uint32_t)(row * 128 + cc * 16);                  \
            CPA16((buf) + SWZ(off), src);                                    \
        }                                                                    \
    } while (0)

#define LDG_H(chunk) do {                                                    \
        int _n = (chunk) * 64 + krow;                                        \
        bool _v = _n < Nn;                                                   \
        const float* _hr = H + (size_t)_n * Ee;                              \
        _Pragma("unroll")                                                    \
        for (int _j = 0; _j < 4; ++_j) {                                     \
            float4 f;                                                        \
            if (!tail) {                                                     \
                f = _v ? __ldcg((const float4*)&_hr[e0 + ecol + 4 * _j])     \
                       : make_float4(0.f, 0.f, 0.f, 0.f);                    \
            } else {                                                         \
                int _e = e0 + ecol + 4 * _j;                                 \
                f.x = (_v && _e + 0 < Ee) ? __ldcg(&_hr[_e + 0]) : 0.f;      \
                f.y = (_v && _e + 1 < Ee) ? __ldcg(&_hr[_e + 1]) : 0.f;      \
                f.z = (_v && _e + 2 < Ee) ? __ldcg(&_hr[_e + 2]) : 0.f;      \
                f.w = (_v && _e + 3 < Ee) ? __ldcg(&_hr[_e + 3]) : 0.f;      \
            }                                                                \
            __nv_bfloat162 p0 = __floats2bfloat162_rn(f.x, f.y);             \
            __nv_bfloat162 p1 = __floats2bfloat162_rn(f.z, f.w);             \
            w[2 * _j]     = *(uint32_t*)&p0;                                 \
            w[2 * _j + 1] = *(uint32_t*)&p1;                                 \
        }                                                                    \
    } while (0)

#define STS_H(buf) do {                                                      \
        uint32_t off = (uint32_t)(krow * 128 + ecol * 2);                    \
        sts128((buf) + SWZ(off),      w[0], w[1], w[2], w[3]);               \
        sts128((buf) + SWZ(off + 16), w[4], w[5], w[6], w[7]);               \
    } while (0)

#define COMPUTE(abuf, bbuf) do {                                             \
        _Pragma("unroll")                                                    \
        for (int k0 = 0; k0 < 64; k0 += 16) {                                \
            uint32_t afr[2][4];                                              \
            _Pragma("unroll")                                                \
            for (int i = 0; i < 2; ++i) {                                    \
                uint32_t off = (uint32_t)((m0 + i * 16 + aRow) * 128         \
                                          + (k0 + aKh) * 2);                 \
                LDSM4(afr[i], (abuf) + SWZ(off));                            \
            }                                                                \
            uint32_t bfr[2][4];                                              \
            _Pragma("unroll")                                                \
            for (int jb = 0; jb < 2; ++jb) {                                 \
                uint32_t off = (uint32_t)((k0 + bKr) * 128                   \
                                          + (n0w + jb * 16 + bNc) * 2);      \
                LDSM4T(bfr[jb], (bbuf) + SWZ(off));                          \
            }                                                                \
            _Pragma("unroll")                                                \
            for (int i = 0; i < 2; ++i)                                      \
                _Pragma("unroll")                                            \
                for (int j = 0; j < 4; ++j)                                  \
                    mma16816(acc[i][j], afr[i],                              \
                             bfr[j >> 1][(j & 1) * 2],                       \
                             bfr[j >> 1][(j & 1) * 2 + 1]);                  \
        }                                                                    \
    } while (0)

    // ---- pipeline (double-buffered) ----
    LOAD_A(sb, c0);
    CPA_COMMIT();
    LDG_H(c0);
    CPA_WAIT0();
    STS_H(sb + 32768);
    __syncthreads();

    for (int cc = 0; cc < nch; ++cc) {
        const int b = cc & 1;
        const uint32_t aCur = sb + b * 16384;
        const uint32_t bCur = sb + 32768 + b * 8192;
        const uint32_t aNxt = sb + (b ^ 1) * 16384;
        const uint32_t bNxt = sb + 32768 + (b ^ 1) * 8192;
        const bool has = (cc + 1) < nch;
        if (has) {
            LOAD_A(aNxt, c0 + cc + 1);
            CPA_COMMIT();
            LDG_H(c0 + cc + 1);
        }
        COMPUTE(aCur, bCur);
        if (has) {
            CPA_WAIT0();
            STS_H(bNxt);
        }
        __syncthreads();
    }

    // ---- write partials: g_Mpart[sl][d][e] ----
    #pragma unroll
    for (int i = 0; i < 2; ++i) {
        #pragma unroll
        for (int j = 0; j < 4; ++j) {
            int d = m0 + i * 16 + (lane >> 2);
            int e = e0 + n0w + j * 8 + (lane & 3) * 2;
            size_t base = ((size_t)(sl * DD + d)) * EPITCH + e;
            *(float2*)&g_Mpart[base] = make_float2(acc[i][j][0], acc[i][j][1]);
            *(float2*)&g_Mpart[base + (size_t)8 * EPITCH] =
                make_float2(acc[i][j][2], acc[i][j][3]);
        }
    }
}

// ---------------- pass 3 + fused final reduce --------------------------------
__global__ void __launch_bounds__(256, 8)
pass3_kernel(float* __restrict__ out, int Nn) {
    __shared__ float r[256];
    __shared__ int isLast;
    const int t = threadIdx.x;
    const int d = blockIdx.x / 20;
    const int e = (blockIdx.x % 20) * 256 + t;
    float v = 0.f;
    #pragma unroll
    for (int j = 0; j < NSL; ++j)
        v += g_Mpart[((size_t)(j * DD + d)) * EPITCH + e];
    r[t] = v * v * g_deinv[e];
    __syncthreads();
    #pragma unroll
    for (int s = 128; s > 0; s >>= 1) {
        if (t < s) r[t] += r[t + s];
        __syncthreads();
    }
    if (t == 0) {
        g_blocksum[blockIdx.x] = r[0];
        __threadfence();
        int done = atomicAdd(&g_count, 1);
        isLast = (done == (int)gridDim.x - 1);
    }
    __syncthreads();
    if (isLast) {
        float acc = 0.f;
        for (int i = t; i < NPREP; i += 256) acc += g_f2sum[i];
        for (int i = t; i < 2560; i += 256) acc -= g_blocksum[i];
        r[t] = acc;
        __syncthreads();
        #pragma unroll
        for (int s = 128; s > 0; s >>= 1) {
            if (t < s) r[t] += r[t + s];
            __syncthreads();
        }
        if (t == 0) {
            out[0] = r[0] / (float)Nn;
            g_count = 0;               // reset for next graph replay
            g_prepdone = 0;
        }
    }
}

// ---------------- launch ------------------------------------------------------
extern "C" void kernel_launch(void* const* d_in, const int* in_sizes, int n_in,
                              void* d_out, int out_size) {
    const float* F  = (const float*)d_in[0];   // [N,128]
    const float* H  = (const float*)d_in[1];   // [N,E]
    const float* Dv = (const float*)d_in[2];   // [N,N]
    const float* De = (const float*)d_in[3];   // [E,E]
    float* out = (float*)d_out;

    int Nn = in_sizes[0] / DD;                 // 10000
    int Ee = in_sizes[1] / Nn;                 // 5000

    cudaFuncSetAttribute(gemm_kernel, cudaFuncAttributeMaxDynamicSharedMemorySize,
                         49152);

    gemm_kernel<<<444, 256, 49152>>>(H, F, Dv, De, Nn, Ee);
    pass3_kernel<<<2560, 256>>>(out, Nn);
}

// round 13
// speedup vs baseline: 1.6572x; 1.0218x over previous
#include <cuda_runtime.h>
#include <cuda_bf16.h>
#include <stdint.h>
#include <math.h>

#define EPSF 1e-8f
#define DD 128               // d
#define KPAD 10048           // 314*32 padded K (= problem N)
#define NCHUNKS 157          // 64-k chunks
#define EPAD 5120
#define EPITCH 5120
#define NSL 6                // max K slices
#define NPREP 314

// ---------------- static device scratch (no allocation) ----------------------
static __device__ __align__(256) __nv_bfloat16 g_FsT[DD * KPAD];     // Fs^T K-major bf16
static __device__ __align__(256) float g_Mpart[NSL * DD * EPITCH];   // 15.7 MB (zero-init)
static __device__ float g_deinv[EPAD];
static __device__ float g_blocksum[640];
static __device__ float g_f2sum[NPREP + 2];
static __device__ int   g_count;
static __device__ int   g_prepdone;

// ---------------- helpers ----------------------------------------------------
__device__ __forceinline__ uint32_t smem_u32(const void* p) {
    uint32_t a;
    asm("{ .reg .u64 t; cvta.to.shared.u64 t, %1; cvt.u32.u64 %0, t; }"
        : "=r"(a) : "l"(p));
    return a;
}
#define SWZ(o) ((o) ^ (((o) >> 3) & 0x70))

__device__ __forceinline__ void sts128(uint32_t addr, uint32_t a, uint32_t b,
                                       uint32_t c, uint32_t d) {
    asm volatile("st.shared.v4.b32 [%0], {%1,%2,%3,%4};"
                 :: "r"(addr), "r"(a), "r"(b), "r"(c), "r"(d) : "memory");
}
#define CPA16(dst, src) \
    asm volatile("cp.async.cg.shared.global [%0], [%1], 16;" \
                 :: "r"(dst), "l"(src) : "memory")
#define CPA_COMMIT() asm volatile("cp.async.commit_group;" ::: "memory")
#define CPA_WAIT0()  asm volatile("cp.async.wait_group 0;" ::: "memory")

#define LDSM4(r, addr) \
    asm volatile("ldmatrix.sync.aligned.m8n8.x4.shared.b16 {%0,%1,%2,%3}, [%4];" \
                 : "=r"((r)[0]), "=r"((r)[1]), "=r"((r)[2]), "=r"((r)[3]) : "r"(addr))
#define LDSM4T(r, addr) \
    asm volatile("ldmatrix.sync.aligned.m8n8.x4.trans.shared.b16 {%0,%1,%2,%3}, [%4];" \
                 : "=r"((r)[0]), "=r"((r)[1]), "=r"((r)[2]), "=r"((r)[3]) : "r"(addr))

__device__ __forceinline__ void mma16816(float* c, const uint32_t* a,
                                         uint32_t b0, uint32_t b1) {
    asm volatile(
        "mma.sync.aligned.m16n8k16.row.col.f32.bf16.bf16.f32 "
        "{%0,%1,%2,%3}, {%4,%5,%6,%7}, {%8,%9}, {%0,%1,%2,%3};"
        : "+f"(c[0]), "+f"(c[1]), "+f"(c[2]), "+f"(c[3])
        : "r"(a[0]), "r"(a[1]), "r"(a[2]), "r"(a[3]), "r"(b0), "r"(b1));
}

// ---------------- GEMM with fused prep phase ---------------------------------
// Grid 444 = one wave at occ 3. Placement law: bids {b, b+148, b+296} share an
// SM, so heavy (5-slice) units go to bids 0..147 (+2 leftovers) and light
// (6-slice) units fill the rest -> ~84 chunk-units per SM, balanced.
__global__ void __launch_bounds__(256, 3)
gemm_kernel(const float* __restrict__ H, const float* __restrict__ F,
            const float* __restrict__ Dv, const float* __restrict__ De,
            int Nn, int Ee) {
    extern __shared__ __align__(1024) char smem[];
    const uint32_t sb = smem_u32(smem);
    const int t = threadIdx.x;
    const int bid = blockIdx.x;

    // ================= phase 1: fused prep =================
    {
        __nv_bfloat16 (*s)[132] = (__nv_bfloat16(*)[132])smem;
        float* red  = (float*)(smem + 9216);
        float* dvis = (float*)(smem + 10240);
        if (bid < NPREP) {
            const int n0 = bid * 32;
            if (t < 32) {
                int n = n0 + t;
                dvis[t] = (n < Nn) ? rsqrtf(Dv[(size_t)n * Nn + n] + EPSF) : 0.f;
            }
            __syncthreads();
            float f2 = 0.f;
            #pragma unroll
            for (int i = 0; i < 4; ++i) {
                int g = t + 256 * i;
                int nl = g >> 5;
                int d4 = (g & 31) * 4;
                int n = n0 + nl;
                float4 v = make_float4(0.f, 0.f, 0.f, 0.f);
                float sc = 0.f;
                if (n < Nn) { v = *(const float4*)&F[(size_t)n * DD + d4]; sc = dvis[nl]; }
                f2 += v.x * v.x + v.y * v.y + v.z * v.z + v.w * v.w;
                s[nl][d4 + 0] = __float2bfloat16(v.x * sc);
                s[nl][d4 + 1] = __float2bfloat16(v.y * sc);
                s[nl][d4 + 2] = __float2bfloat16(v.z * sc);
                s[nl][d4 + 3] = __float2bfloat16(v.w * sc);
            }
            __syncthreads();
            {
                int d = t >> 1;
                int nh = (t & 1) * 16;
                uint32_t w2[8];
                #pragma unroll
                for (int j = 0; j < 8; ++j) {
                    __nv_bfloat162 p;
                    p.x = s[nh + 2 * j][d];
                    p.y = s[nh + 2 * j + 1][d];
                    w2[j] = *(uint32_t*)&p;
                }
                uint4* dst = (uint4*)&g_FsT[(size_t)d * KPAD + n0 + nh];
                dst[0] = make_uint4(w2[0], w2[1], w2[2], w2[3]);
                dst[1] = make_uint4(w2[4], w2[5], w2[6], w2[7]);
            }
            red[t] = f2;
            __syncthreads();
            #pragma unroll
            for (int s2 = 128; s2 > 0; s2 >>= 1) {
                if (t < s2) red[t] += red[t + s2];
                __syncthreads();
            }
            if (t == 0) {
                g_f2sum[bid] = red[0];
                __threadfence();
                atomicAdd(&g_prepdone, 1);
            }
        } else if (bid < NPREP + 20) {
            int e = (bid - NPREP) * 256 + t;
            if (e < EPAD)
                g_deinv[e] = (e < Ee) ? 1.f / (De[(size_t)e * Ee + e] + EPSF) : 0.f;
        }
        if (t == 0) {
            while (atomicAdd(&g_prepdone, 0) < NPREP) {}
        }
        __syncthreads();
        __threadfence();
    }

    // ================= phase 2: gemm =================
    const int lane = t & 31;
    const int wid = t >> 5;
    const int wm = wid & 3;            // 4 m-warps (32 d each)
    const int wn = wid >> 2;           // 2 n-warps (32 e each)
    const int m0 = wm * 32;
    const int n0w = wn * 32;

    // ---- balanced work mapping ----
    // heavy units: tiles 49..78, 5 slices (150 units, ~31 chunks each)
    // light units: tiles 0..48, 6 slices (294 units, ~26 chunks each)
    int et, sl, nsl;
    {
        int hidx = -1, lidx = -1;
        if (bid < 148)       hidx = bid;                 // heavy 0..147
        else if (bid < 296)  lidx = bid - 148;           // light 0..147
        else if (bid < 298)  hidx = 148 + (bid - 296);   // heavy 148..149
        else                 lidx = 148 + (bid - 298);   // light 148..293
        if (hidx >= 0) { et = 49 + hidx / 5; sl = hidx % 5; nsl = 5; }
        else           { et = lidx / 6;      sl = lidx % 6; nsl = 6; }
    }
    const int e0 = et * 64;
    const int c0 = (sl * NCHUNKS) / nsl;
    const int c1 = ((sl + 1) * NCHUNKS) / nsl;
    const int nch = c1 - c0;
    const bool tail = (e0 + 64 > Ee);

    const int krow = t >> 2;           // 0..63
    const int ecol = (t & 3) * 16;     // 16 e per thread

    float acc[2][4][4];
    #pragma unroll
    for (int i = 0; i < 2; ++i)
        #pragma unroll
        for (int j = 0; j < 4; ++j)
            #pragma unroll
            for (int q = 0; q < 4; ++q) acc[i][j][q] = 0.f;

    const int aRow = (lane & 15);
    const int aKh  = (lane >> 4) * 8;
    const int bKr  = (lane & 15);
    const int bNc  = (lane >> 4) * 8;

    uint32_t w[8];                     // converted B staging (bf16x2)

#define LOAD_A(buf, chunk) do {                                              \
        int _cg = (chunk);                                                   \
        _Pragma("unroll")                                                    \
        for (int _i = 0; _i < 4; ++_i) {                                     \
            int pos = t + 256 * _i;                                          \
            int row = pos >> 3;                                              \
            int cc  = pos & 7;                                               \
            const __nv_bfloat16* src = &g_FsT[(size_t)row * KPAD + _cg * 64 + cc * 8]; \
            uint32_t off = (uint32_t)(row * 128 + cc * 16);                  \
            CPA16((buf) + SWZ(off), src);                                    \
        }                                                                    \
    } while (0)

#define LDG_H(chunk) do {                                                    \
        int _n = (chunk) * 64 + krow;                                        \
        bool _v = _n < Nn;                                                   \
        const float* _hr = H + (size_t)_n * Ee;                              \
        _Pragma("unroll")                                                    \
        for (int _j = 0; _j < 4; ++_j) {                                     \
            float4 f;                                                        \
            if (!tail) {                                                     \
                f = _v ? __ldcg((const float4*)&_hr[e0 + ecol + 4 * _j])     \
                       : make_float4(0.f, 0.f, 0.f, 0.f);                    \
            } else {                                                         \
                int _e = e0 + ecol + 4 * _j;                                 \
                f.x = (_v && _e + 0 < Ee) ? __ldcg(&_hr[_e + 0]) : 0.f;      \
                f.y = (_v && _e + 1 < Ee) ? __ldcg(&_hr[_e + 1]) : 0.f;      \
                f.z = (_v && _e + 2 < Ee) ? __ldcg(&_hr[_e + 2]) : 0.f;      \
                f.w = (_v && _e + 3 < Ee) ? __ldcg(&_hr[_e + 3]) : 0.f;      \
            }                                                                \
            __nv_bfloat162 p0 = __floats2bfloat162_rn(f.x, f.y);             \
            __nv_bfloat162 p1 = __floats2bfloat162_rn(f.z, f.w);             \
            w[2 * _j]     = *(uint32_t*)&p0;                                 \
            w[2 * _j + 1] = *(uint32_t*)&p1;                                 \
        }                                                                    \
    } while (0)

#define STS_H(buf) do {                                                      \
        uint32_t off = (uint32_t)(krow * 128 + ecol * 2);                    \
        sts128((buf) + SWZ(off),      w[0], w[1], w[2], w[3]);               \
        sts128((buf) + SWZ(off + 16), w[4], w[5], w[6], w[7]);               \
    } while (0)

#define COMPUTE(abuf, bbuf) do {                                             \
        _Pragma("unroll")                                                    \
        for (int k0 = 0; k0 < 64; k0 += 16) {                                \
            uint32_t afr[2][4];                                              \
            _Pragma("unroll")                                                \
            for (int i = 0; i < 2; ++i) {                                    \
                uint32_t off = (uint32_t)((m0 + i * 16 + aRow) * 128         \
                                          + (k0 + aKh) * 2);                 \
                LDSM4(afr[i], (abuf) + SWZ(off));                            \
            }                                                                \
            uint32_t bfr[2][4];                                              \
            _Pragma("unroll")                                                \
            for (int jb = 0; jb < 2; ++jb) {                                 \
                uint32_t off = (uint32_t)((k0 + bKr) * 128                   \
                                          + (n0w + jb * 16 + bNc) * 2);      \
                LDSM4T(bfr[jb], (bbuf) + SWZ(off));                          \
            }                                                                \
            _Pragma("unroll")                                                \
            for (int i = 0; i < 2; ++i)                                      \
                _Pragma("unroll")                                            \
                for (int j = 0; j < 4; ++j)                                  \
                    mma16816(acc[i][j], afr[i],                              \
                             bfr[j >> 1][(j & 1) * 2],                       \
                             bfr[j >> 1][(j & 1) * 2 + 1]);                  \
        }                                                                    \
    } while (0)

    // ---- pipeline (double-buffered) ----
    LOAD_A(sb, c0);
    CPA_COMMIT();
    LDG_H(c0);
    CPA_WAIT0();
    STS_H(sb + 32768);
    __syncthreads();

    for (int cc = 0; cc < nch; ++cc) {
        const int b = cc & 1;
        const uint32_t aCur = sb + b * 16384;
        const uint32_t bCur = sb + 32768 + b * 8192;
        const uint32_t aNxt = sb + (b ^ 1) * 16384;
        const uint32_t bNxt = sb + 32768 + (b ^ 1) * 8192;
        const bool has = (cc + 1) < nch;
        if (has) {
            LOAD_A(aNxt, c0 + cc + 1);
            CPA_COMMIT();
            LDG_H(c0 + cc + 1);
        }
        COMPUTE(aCur, bCur);
        if (has) {
            CPA_WAIT0();
            STS_H(bNxt);
        }
        __syncthreads();
    }

    // ---- write partials: g_Mpart[sl][d][e] ----
    #pragma unroll
    for (int i = 0; i < 2; ++i) {
        #pragma unroll
        for (int j = 0; j < 4; ++j) {
            int d = m0 + i * 16 + (lane >> 2);
            int e = e0 + n0w + j * 8 + (lane & 3) * 2;
            size_t base = ((size_t)(sl * DD + d)) * EPITCH + e;
            *(float2*)&g_Mpart[base] = make_float2(acc[i][j][0], acc[i][j][1]);
            *(float2*)&g_Mpart[base + (size_t)8 * EPITCH] =
                make_float2(acc[i][j][2], acc[i][j][3]);
        }
    }
}

// ---------------- pass 3 (float4) + fused final reduce -----------------------
// grid 640: d = bid/5, e4 = (bid%5)*256 + t (4 e-values per thread).
__global__ void __launch_bounds__(256, 8)
pass3_kernel(float* __restrict__ out, int Nn) {
    __shared__ float r[256];
    __shared__ int isLast;
    const int t = threadIdx.x;
    const int d = blockIdx.x / 5;
    const int e = ((blockIdx.x % 5) * 256 + t) * 4;
    float4 v = make_float4(0.f, 0.f, 0.f, 0.f);
    #pragma unroll
    for (int j = 0; j < NSL; ++j) {
        float4 m = *(const float4*)&g_Mpart[((size_t)(j * DD + d)) * EPITCH + e];
        v.x += m.x; v.y += m.y; v.z += m.z; v.w += m.w;
    }
    float4 di = *(const float4*)&g_deinv[e];
    r[t] = v.x * v.x * di.x + v.y * v.y * di.y + v.z * v.z * di.z
         + v.w * v.w * di.w;
    __syncthreads();
    #pragma unroll
    for (int s = 128; s > 0; s >>= 1) {
        if (t < s) r[t] += r[t + s];
        __syncthreads();
    }
    if (t == 0) {
        g_blocksum[blockIdx.x] = r[0];
        __threadfence();
        int done = atomicAdd(&g_count, 1);
        isLast = (done == (int)gridDim.x - 1);
    }
    __syncthreads();
    if (isLast) {
        float acc = 0.f;
        for (int i = t; i < NPREP; i += 256) acc += g_f2sum[i];
        for (int i = t; i < 640; i += 256) acc -= g_blocksum[i];
        r[t] = acc;
        __syncthreads();
        #pragma unroll
        for (int s = 128; s > 0; s >>= 1) {
            if (t < s) r[t] += r[t + s];
            __syncthreads();
        }
        if (t == 0) {
            out[0] = r[0] / (float)Nn;
            g_count = 0;               // reset for next graph replay
            g_prepdone = 0;
        }
    }
}

// ---------------- launch ------------------------------------------------------
extern "C" void kernel_launch(void* const* d_in, const int* in_sizes, int n_in,
                              void* d_out, int out_size) {
    const float* F  = (const float*)d_in[0];   // [N,128]
    const float* H  = (const float*)d_in[1];   // [N,E]
    const float* Dv = (const float*)d_in[2];   // [N,N]
    const float* De = (const float*)d_in[3];   // [E,E]
    float* out = (float*)d_out;

    int Nn = in_sizes[0] / DD;                 // 10000
    int Ee = in_sizes[1] / Nn;                 // 5000

    cudaFuncSetAttribute(gemm_kernel, cudaFuncAttributeMaxDynamicSharedMemorySize,
                         49152);

    gemm_kernel<<<444, 256, 49152>>>(H, F, Dv, De, Nn, Ee);
    pass3_kernel<<<640, 256>>>(out, Nn);
}

// round 14
// speedup vs baseline: 1.7069x; 1.0300x over previous
#include <cuda_runtime.h>
#include <cuda_bf16.h>
#include <stdint.h>
#include <math.h>

#define EPSF 1e-8f
#define DD 128               // d
#define KPAD 10048           // 314*32 padded K (= problem N)
#define NCHUNKS 157          // 64-k chunks
#define EPAD 5120
#define EPITCH 5120
#define NSL 6                // max K slices
#define NPREP 314

// ---------------- static device scratch (no allocation) ----------------------
static __device__ __align__(256) __nv_bfloat16 g_FsT[DD * KPAD];      // Fs^T K-major bf16
static __device__ __align__(256) __nv_bfloat16 g_Mpart[NSL * DD * EPITCH]; // 7.9 MB bf16
static __device__ float g_deinv[EPAD];
static __device__ float g_blocksum[640];
static __device__ float g_f2sum[NPREP + 2];
static __device__ int   g_count;
static __device__ int   g_prepdone;

// ---------------- helpers ----------------------------------------------------
__device__ __forceinline__ uint32_t smem_u32(const void* p) {
    uint32_t a;
    asm("{ .reg .u64 t; cvta.to.shared.u64 t, %1; cvt.u32.u64 %0, t; }"
        : "=r"(a) : "l"(p));
    return a;
}
#define SWZ(o) ((o) ^ (((o) >> 3) & 0x70))

__device__ __forceinline__ void sts128(uint32_t addr, uint32_t a, uint32_t b,
                                       uint32_t c, uint32_t d) {
    asm volatile("st.shared.v4.b32 [%0], {%1,%2,%3,%4};"
                 :: "r"(addr), "r"(a), "r"(b), "r"(c), "r"(d) : "memory");
}
#define CPA16(dst, src) \
    asm volatile("cp.async.cg.shared.global [%0], [%1], 16;" \
                 :: "r"(dst), "l"(src) : "memory")
#define CPA_COMMIT() asm volatile("cp.async.commit_group;" ::: "memory")
#define CPA_WAIT0()  asm volatile("cp.async.wait_group 0;" ::: "memory")

#define LDSM4(r, addr) \
    asm volatile("ldmatrix.sync.aligned.m8n8.x4.shared.b16 {%0,%1,%2,%3}, [%4];" \
                 : "=r"((r)[0]), "=r"((r)[1]), "=r"((r)[2]), "=r"((r)[3]) : "r"(addr))
#define LDSM4T(r, addr) \
    asm volatile("ldmatrix.sync.aligned.m8n8.x4.trans.shared.b16 {%0,%1,%2,%3}, [%4];" \
                 : "=r"((r)[0]), "=r"((r)[1]), "=r"((r)[2]), "=r"((r)[3]) : "r"(addr))

__device__ __forceinline__ void mma16816(float* c, const uint32_t* a,
                                         uint32_t b0, uint32_t b1) {
    asm volatile(
        "mma.sync.aligned.m16n8k16.row.col.f32.bf16.bf16.f32 "
        "{%0,%1,%2,%3}, {%4,%5,%6,%7}, {%8,%9}, {%0,%1,%2,%3};"
        : "+f"(c[0]), "+f"(c[1]), "+f"(c[2]), "+f"(c[3])
        : "r"(a[0]), "r"(a[1]), "r"(a[2]), "r"(a[3]), "r"(b0), "r"(b1));
}

// ---------------- GEMM with fused prep phase ---------------------------------
// Grid 444 = one wave at occ 3. Heavy (5-slice) units on bids 0..147 (+2),
// light (6-slice) on the rest -> per-SM chunk-units balanced (~84).
__global__ void __launch_bounds__(256, 3)
gemm_kernel(const float* __restrict__ H, const float* __restrict__ F,
            const float* __restrict__ Dv, const float* __restrict__ De,
            int Nn, int Ee) {
    extern __shared__ __align__(1024) char smem[];
    const uint32_t sb = smem_u32(smem);
    const int t = threadIdx.x;
    const int bid = blockIdx.x;

    // ================= phase 1: fused prep =================
    {
        __nv_bfloat16 (*s)[132] = (__nv_bfloat16(*)[132])smem;
        float* red  = (float*)(smem + 9216);
        float* dvis = (float*)(smem + 10240);
        if (bid < NPREP) {
            const int n0 = bid * 32;
            if (t < 32) {
                int n = n0 + t;
                dvis[t] = (n < Nn) ? rsqrtf(Dv[(size_t)n * Nn + n] + EPSF) : 0.f;
            }
            __syncthreads();
            float f2 = 0.f;
            #pragma unroll
            for (int i = 0; i < 4; ++i) {
                int g = t + 256 * i;
                int nl = g >> 5;
                int d4 = (g & 31) * 4;
                int n = n0 + nl;
                float4 v = make_float4(0.f, 0.f, 0.f, 0.f);
                float sc = 0.f;
                if (n < Nn) { v = *(const float4*)&F[(size_t)n * DD + d4]; sc = dvis[nl]; }
                f2 += v.x * v.x + v.y * v.y + v.z * v.z + v.w * v.w;
                s[nl][d4 + 0] = __float2bfloat16(v.x * sc);
                s[nl][d4 + 1] = __float2bfloat16(v.y * sc);
                s[nl][d4 + 2] = __float2bfloat16(v.z * sc);
                s[nl][d4 + 3] = __float2bfloat16(v.w * sc);
            }
            __syncthreads();
            {
                int d = t >> 1;
                int nh = (t & 1) * 16;
                uint32_t w2[8];
                #pragma unroll
                for (int j = 0; j < 8; ++j) {
                    __nv_bfloat162 p;
                    p.x = s[nh + 2 * j][d];
                    p.y = s[nh + 2 * j + 1][d];
                    w2[j] = *(uint32_t*)&p;
                }
                uint4* dst = (uint4*)&g_FsT[(size_t)d * KPAD + n0 + nh];
                dst[0] = make_uint4(w2[0], w2[1], w2[2], w2[3]);
                dst[1] = make_uint4(w2[4], w2[5], w2[6], w2[7]);
            }
            red[t] = f2;
            __syncthreads();
            #pragma unroll
            for (int s2 = 128; s2 > 0; s2 >>= 1) {
                if (t < s2) red[t] += red[t + s2];
                __syncthreads();
            }
            if (t == 0) {
                g_f2sum[bid] = red[0];
                __threadfence();
                atomicAdd(&g_prepdone, 1);
            }
        } else if (bid < NPREP + 20) {
            int e = (bid - NPREP) * 256 + t;
            if (e < EPAD)
                g_deinv[e] = (e < Ee) ? 1.f / (De[(size_t)e * Ee + e] + EPSF) : 0.f;
        }
    }

    // ================= phase 2: gemm =================
    const int lane = t & 31;
    const int wid = t >> 5;
    const int wm = wid & 3;            // 4 m-warps (32 d each)
    const int wn = wid >> 2;           // 2 n-warps (32 e each)
    const int m0 = wm * 32;
    const int n0w = wn * 32;

    // ---- balanced work mapping ----
    int et, sl, nsl;
    {
        int hidx = -1, lidx = -1;
        if (bid < 148)       hidx = bid;                 // heavy 0..147
        else if (bid < 296)  lidx = bid - 148;           // light 0..147
        else if (bid < 298)  hidx = 148 + (bid - 296);   // heavy 148..149
        else                 lidx = 148 + (bid - 298);   // light 148..293
        if (hidx >= 0) { et = 49 + hidx / 5; sl = hidx % 5; nsl = 5; }
        else           { et = lidx / 6;      sl = lidx % 6; nsl = 6; }
    }
    const int e0 = et * 64;
    const int c0 = (sl * NCHUNKS) / nsl;
    const int c1 = ((sl + 1) * NCHUNKS) / nsl;
    const int nch = c1 - c0;
    const bool tail = (e0 + 64 > Ee);

    const int krow = t >> 2;           // 0..63
    const int ecol = (t & 3) * 16;     // 16 e per thread

    float acc[2][4][4];
    #pragma unroll
    for (int i = 0; i < 2; ++i)
        #pragma unroll
        for (int j = 0; j < 4; ++j)
            #pragma unroll
            for (int q = 0; q < 4; ++q) acc[i][j][q] = 0.f;

    const int aRow = (lane & 15);
    const int aKh  = (lane >> 4) * 8;
    const int bKr  = (lane & 15);
    const int bNc  = (lane >> 4) * 8;

    uint32_t w[8];                     // converted B staging (bf16x2)

#define LOAD_A(buf, chunk) do {                                              \
        int _cg = (chunk);                                                   \
        _Pragma("unroll")                                                    \
        for (int _i = 0; _i < 4; ++_i) {                                     \
            int pos = t + 256 * _i;                                          \
            int row = pos >> 3;                                              \
            int cc  = pos & 7;                                               \
            const __nv_bfloat16* src = &g_FsT[(size_t)row * KPAD + _cg * 64 + cc * 8]; \
            uint32_t off = (uint32_t)(row * 128 + cc * 16);                  \
            CPA16((buf) + SWZ(off), src);                                    \
        }                                                                    \
    } while (0)

#define LDG_H(chunk) do {                                                    \
        int _n = (chunk) * 64 + krow;                                        \
        bool _v = _n < Nn;                                                   \
        const float* _hr = H + (size_t)_n * Ee;                              \
        _Pragma("unroll")                                                    \
        for (int _j = 0; _j < 4; ++_j) {                                     \
            float4 f;                                                        \
            if (!tail) {                                                     \
                f = _v ? __ldcg((const float4*)&_hr[e0 + ecol + 4 * _j])     \
                       : make_float4(0.f, 0.f, 0.f, 0.f);                    \
            } else {                                                         \
                int _e = e0 + ecol + 4 * _j;                                 \
                f.x = (_v && _e + 0 < Ee) ? __ldcg(&_hr[_e + 0]) : 0.f;      \
                f.y = (_v && _e + 1 < Ee) ? __ldcg(&_hr[_e + 1]) : 0.f;      \
                f.z = (_v && _e + 2 < Ee) ? __ldcg(&_hr[_e + 2]) : 0.f;      \
                f.w = (_v && _e + 3 < Ee) ? __ldcg(&_hr[_e + 3]) : 0.f;      \
            }                                                                \
            __nv_bfloat162 p0 = __floats2bfloat162_rn(f.x, f.y);             \
            __nv_bfloat162 p1 = __floats2bfloat162_rn(f.z, f.w);             \
            w[2 * _j]     = *(uint32_t*)&p0;                                 \
            w[2 * _j + 1] = *(uint32_t*)&p1;                                 \
        }                                                                    \
    } while (0)

#define STS_H(buf) do {                                                      \
        uint32_t off = (uint32_t)(krow * 128 + ecol * 2);                    \
        sts128((buf) + SWZ(off),      w[0], w[1], w[2], w[3]);               \
        sts128((buf) + SWZ(off + 16), w[4], w[5], w[6], w[7]);               \
    } while (0)

#define COMPUTE(abuf, bbuf) do {                                             \
        _Pragma("unroll")                                                    \
        for (int k0 = 0; k0 < 64; k0 += 16) {                                \
            uint32_t afr[2][4];                                              \
            _Pragma("unroll")                                                \
            for (int i = 0; i < 2; ++i) {                                    \
                uint32_t off = (uint32_t)((m0 + i * 16 + aRow) * 128         \
                                          + (k0 + aKh) * 2);                 \
                LDSM4(afr[i], (abuf) + SWZ(off));                            \
            }                                                                \
            uint32_t bfr[2][4];                                              \
            _Pragma("unroll")                                                \
            for (int jb = 0; jb < 2; ++jb) {                                 \
                uint32_t off = (uint32_t)((k0 + bKr) * 128                   \
                                          + (n0w + jb * 16 + bNc) * 2);      \
                LDSM4T(bfr[jb], (bbuf) + SWZ(off));                          \
            }                                                                \
            _Pragma("unroll")                                                \
            for (int i = 0; i < 2; ++i)                                      \
                _Pragma("unroll")                                            \
                for (int j = 0; j < 4; ++j)                                  \
                    mma16816(acc[i][j], afr[i],                              \
                             bfr[j >> 1][(j & 1) * 2],                       \
                             bfr[j >> 1][(j & 1) * 2 + 1]);                  \
        }                                                                    \
    } while (0)

    // ---- overlap: issue first H tile load BEFORE the prep spin barrier ----
    LDG_H(c0);

    // ---- global spin barrier (all 444 CTAs resident at occ 3 -> safe) ----
    if (t == 0) {
        while (atomicAdd(&g_prepdone, 0) < NPREP) {}
    }
    __syncthreads();
    __threadfence();

    // ---- pipeline (double-buffered) ----
    LOAD_A(sb, c0);
    CPA_COMMIT();
    CPA_WAIT0();
    STS_H(sb + 32768);
    __syncthreads();

    for (int cc = 0; cc < nch; ++cc) {
        const int b = cc & 1;
        const uint32_t aCur = sb + b * 16384;
        const uint32_t bCur = sb + 32768 + b * 8192;
        const uint32_t aNxt = sb + (b ^ 1) * 16384;
        const uint32_t bNxt = sb + 32768 + (b ^ 1) * 8192;
        const bool has = (cc + 1) < nch;
        if (has) {
            LOAD_A(aNxt, c0 + cc + 1);
            CPA_COMMIT();
            LDG_H(c0 + cc + 1);
        }
        COMPUTE(aCur, bCur);
        if (has) {
            CPA_WAIT0();
            STS_H(bNxt);
        }
        __syncthreads();
    }

    // ---- write partials as bf16: g_Mpart[sl][d][e] ----
    #pragma unroll
    for (int i = 0; i < 2; ++i) {
        #pragma unroll
        for (int j = 0; j < 4; ++j) {
            int d = m0 + i * 16 + (lane >> 2);
            int e = e0 + n0w + j * 8 + (lane & 3) * 2;
            size_t base = ((size_t)(sl * DD + d)) * EPITCH + e;
            __nv_bfloat162 p0 = __floats2bfloat162_rn(acc[i][j][0], acc[i][j][1]);
            __nv_bfloat162 p1 = __floats2bfloat162_rn(acc[i][j][2], acc[i][j][3]);
            *(uint32_t*)&g_Mpart[base] = *(uint32_t*)&p0;
            *(uint32_t*)&g_Mpart[base + (size_t)8 * EPITCH] = *(uint32_t*)&p1;
        }
    }
}

// ---------------- pass 3 (bf16 partials) + fused final reduce ----------------
// grid 640: d = bid/5, e = ((bid%5)*256 + t)*4 (4 e-values per thread).
__global__ void __launch_bounds__(256, 8)
pass3_kernel(float* __restrict__ out, int Nn) {
    __shared__ float r[256];
    __shared__ int isLast;
    const int t = threadIdx.x;
    const int d = blockIdx.x / 5;
    const int e = ((blockIdx.x % 5) * 256 + t) * 4;
    float4 v = make_float4(0.f, 0.f, 0.f, 0.f);
    #pragma unroll
    for (int j = 0; j < NSL; ++j) {
        uint2 m = *(const uint2*)&g_Mpart[((size_t)(j * DD + d)) * EPITCH + e];
        float2 lo = __bfloat1622float2(*(__nv_bfloat162*)&m.x);
        float2 hi = __bfloat1622float2(*(__nv_bfloat162*)&m.y);
        v.x += lo.x; v.y += lo.y; v.z += hi.x; v.w += hi.y;
    }
    float4 di = *(const float4*)&g_deinv[e];
    r[t] = v.x * v.x * di.x + v.y * v.y * di.y + v.z * v.z * di.z
         + v.w * v.w * di.w;
    __syncthreads();
    #pragma unroll
    for (int s = 128; s > 0; s >>= 1) {
        if (t < s) r[t] += r[t + s];
        __syncthreads();
    }
    if (t == 0) {
        g_blocksum[blockIdx.x] = r[0];
        __threadfence();
        int done = atomicAdd(&g_count, 1);
        isLast = (done == (int)gridDim.x - 1);
    }
    __syncthreads();
    if (isLast) {
        float acc = 0.f;
        for (int i = t; i < NPREP; i += 256) acc += g_f2sum[i];
        for (int i = t; i < 640; i += 256) acc -= g_blocksum[i];
        r[t] = acc;
        __syncthreads();
        #pragma unroll
        for (int s = 128; s > 0; s >>= 1) {
            if (t < s) r[t] += r[t + s];
            __syncthreads();
        }
        if (t == 0) {
            out[0] = r[0] / (float)Nn;
            g_count = 0;               // reset for next graph replay
            g_prepdone = 0;
        }
    }
}

// ---------------- launch ------------------------------------------------------
extern "C" void kernel_launch(void* const* d_in, const int* in_sizes, int n_in,
                              void* d_out, int out_size) {
    const float* F  = (const float*)d_in[0];   // [N,128]
    const float* H  = (const float*)d_in[1];   // [N,E]
    const float* Dv = (const float*)d_in[2];   // [N,N]
    const float* De = (const float*)d_in[3];   // [E,E]
    float* out = (float*)d_out;

    int Nn = in_sizes[0] / DD;                 // 10000
    int Ee = in_sizes[1] / Nn;                 // 5000

    cudaFuncSetAttribute(gemm_kernel, cudaFuncAttributeMaxDynamicSharedMemorySize,
                         49152);

    gemm_kernel<<<444, 256, 49152>>>(H, F, Dv, De, Nn, Ee);
    pass3_kernel<<<640, 256>>>(out, Nn);
}

// round 15
// speedup vs baseline: 1.7640x; 1.0335x over previous
#include <cuda_runtime.h>
#include <cuda_bf16.h>
#include <stdint.h>
#include <math.h>

#define EPSF 1e-8f
#define DD 128               // d
#define KPAD 10048           // 314*32 padded K (= problem N)
#define NCHUNKS 157          // 64-k chunks
#define EPAD 5120
#define EPITCH 5120
#define NSL 6                // max K slices
#define NPREP 314
#define NTILES 79

// ---------------- static device scratch (no allocation) ----------------------
static __device__ __align__(256) __nv_bfloat16 g_FsT[DD * KPAD];      // Fs^T K-major bf16
static __device__ __align__(256) __nv_bfloat16 g_Mpart[NSL * DD * EPITCH]; // 7.9 MB bf16
static __device__ float g_deinv[EPAD];
static __device__ float g_blocksum[NTILES + 1];
static __device__ float g_f2sum[NPREP + 2];
static __device__ int   g_tilecnt[NTILES + 1];
static __device__ int   g_donecnt;
static __device__ int   g_prepdone;

// ---------------- helpers ----------------------------------------------------
__device__ __forceinline__ uint32_t smem_u32(const void* p) {
    uint32_t a;
    asm("{ .reg .u64 t; cvta.to.shared.u64 t, %1; cvt.u32.u64 %0, t; }"
        : "=r"(a) : "l"(p));
    return a;
}
#define SWZ(o) ((o) ^ (((o) >> 3) & 0x70))

__device__ __forceinline__ void sts128(uint32_t addr, uint32_t a, uint32_t b,
                                       uint32_t c, uint32_t d) {
    asm volatile("st.shared.v4.b32 [%0], {%1,%2,%3,%4};"
                 :: "r"(addr), "r"(a), "r"(b), "r"(c), "r"(d) : "memory");
}
#define CPA16(dst, src) \
    asm volatile("cp.async.cg.shared.global [%0], [%1], 16;" \
                 :: "r"(dst), "l"(src) : "memory")
#define CPA_COMMIT() asm volatile("cp.async.commit_group;" ::: "memory")
#define CPA_WAIT0()  asm volatile("cp.async.wait_group 0;" ::: "memory")

#define LDSM4(r, addr) \
    asm volatile("ldmatrix.sync.aligned.m8n8.x4.shared.b16 {%0,%1,%2,%3}, [%4];" \
                 : "=r"((r)[0]), "=r"((r)[1]), "=r"((r)[2]), "=r"((r)[3]) : "r"(addr))
#define LDSM4T(r, addr) \
    asm volatile("ldmatrix.sync.aligned.m8n8.x4.trans.shared.b16 {%0,%1,%2,%3}, [%4];" \
                 : "=r"((r)[0]), "=r"((r)[1]), "=r"((r)[2]), "=r"((r)[3]) : "r"(addr))

__device__ __forceinline__ void mma16816(float* c, const uint32_t* a,
                                         uint32_t b0, uint32_t b1) {
    asm volatile(
        "mma.sync.aligned.m16n8k16.row.col.f32.bf16.bf16.f32 "
        "{%0,%1,%2,%3}, {%4,%5,%6,%7}, {%8,%9}, {%0,%1,%2,%3};"
        : "+f"(c[0]), "+f"(c[1]), "+f"(c[2]), "+f"(c[3])
        : "r"(a[0]), "r"(a[1]), "r"(a[2]), "r"(a[3]), "r"(b0), "r"(b1));
}

// ---------------- single fused kernel: prep + GEMM + reduce ------------------
// Grid 444 = one wave at occ 3. Heavy (5-slice) units on bids 0..147 (+2),
// light (6-slice) on the rest -> per-SM chunk-units balanced (~84).
__global__ void __launch_bounds__(256, 3)
gemm_kernel(const float* __restrict__ H, const float* __restrict__ F,
            const float* __restrict__ Dv, const float* __restrict__ De,
            float* __restrict__ out, int Nn, int Ee) {
    extern __shared__ __align__(1024) char smem[];
    const uint32_t sb = smem_u32(smem);
    const int t = threadIdx.x;
    const int bid = blockIdx.x;

    // ================= phase 1: fused prep =================
    {
        __nv_bfloat16 (*s)[132] = (__nv_bfloat16(*)[132])smem;
        float* red  = (float*)(smem + 9216);
        float* dvis = (float*)(smem + 10240);
        if (bid < NPREP) {
            const int n0 = bid * 32;
            if (t < 32) {
                int n = n0 + t;
                dvis[t] = (n < Nn) ? rsqrtf(Dv[(size_t)n * Nn + n] + EPSF) : 0.f;
            }
            __syncthreads();
            float f2 = 0.f;
            #pragma unroll
            for (int i = 0; i < 4; ++i) {
                int g = t + 256 * i;
                int nl = g >> 5;
                int d4 = (g & 31) * 4;
                int n = n0 + nl;
                float4 v = make_float4(0.f, 0.f, 0.f, 0.f);
                float sc = 0.f;
                if (n < Nn) { v = *(const float4*)&F[(size_t)n * DD + d4]; sc = dvis[nl]; }
                f2 += v.x * v.x + v.y * v.y + v.z * v.z + v.w * v.w;
                s[nl][d4 + 0] = __float2bfloat16(v.x * sc);
                s[nl][d4 + 1] = __float2bfloat16(v.y * sc);
                s[nl][d4 + 2] = __float2bfloat16(v.z * sc);
                s[nl][d4 + 3] = __float2bfloat16(v.w * sc);
            }
            __syncthreads();
            {
                int d = t >> 1;
                int nh = (t & 1) * 16;
                uint32_t w2[8];
                #pragma unroll
                for (int j = 0; j < 8; ++j) {
                    __nv_bfloat162 p;
                    p.x = s[nh + 2 * j][d];
                    p.y = s[nh + 2 * j + 1][d];
                    w2[j] = *(uint32_t*)&p;
                }
                uint4* dst = (uint4*)&g_FsT[(size_t)d * KPAD + n0 + nh];
                dst[0] = make_uint4(w2[0], w2[1], w2[2], w2[3]);
                dst[1] = make_uint4(w2[4], w2[5], w2[6], w2[7]);
            }
            red[t] = f2;
            __syncthreads();
            #pragma unroll
            for (int s2 = 128; s2 > 0; s2 >>= 1) {
                if (t < s2) red[t] += red[t + s2];
                __syncthreads();
            }
            if (t == 0) {
                g_f2sum[bid] = red[0];
                __threadfence();
                atomicAdd(&g_prepdone, 1);
            }
        } else if (bid < NPREP + 20) {
            int e = (bid - NPREP) * 256 + t;
            if (e < EPAD)
                g_deinv[e] = (e < Ee) ? 1.f / (De[(size_t)e * Ee + e] + EPSF) : 0.f;
        }
    }

    // ================= phase 2: gemm =================
    const int lane = t & 31;
    const int wid = t >> 5;
    const int wm = wid & 3;            // 4 m-warps (32 d each)
    const int wn = wid >> 2;           // 2 n-warps (32 e each)
    const int m0 = wm * 32;
    const int n0w = wn * 32;

    // ---- balanced work mapping ----
    int et, sl, nsl;
    {
        int hidx = -1, lidx = -1;
        if (bid < 148)       hidx = bid;                 // heavy 0..147
        else if (bid < 296)  lidx = bid - 148;           // light 0..147
        else if (bid < 298)  hidx = 148 + (bid - 296);   // heavy 148..149
        else                 lidx = 148 + (bid - 298);   // light 148..293
        if (hidx >= 0) { et = 49 + hidx / 5; sl = hidx % 5; nsl = 5; }
        else           { et = lidx / 6;      sl = lidx % 6; nsl = 6; }
    }
    const int e0 = et * 64;
    const int c0 = (sl * NCHUNKS) / nsl;
    const int c1 = ((sl + 1) * NCHUNKS) / nsl;
    const int nch = c1 - c0;
    const bool tail = (e0 + 64 > Ee);

    const int krow = t >> 2;           // 0..63
    const int ecol = (t & 3) * 16;     // 16 e per thread

    float acc[2][4][4];
    #pragma unroll
    for (int i = 0; i < 2; ++i)
        #pragma unroll
        for (int j = 0; j < 4; ++j)
            #pragma unroll
            for (int q = 0; q < 4; ++q) acc[i][j][q] = 0.f;

    const int aRow = (lane & 15);
    const int aKh  = (lane >> 4) * 8;
    const int bKr  = (lane & 15);
    const int bNc  = (lane >> 4) * 8;

    uint32_t w[8];                     // converted B staging (bf16x2)

#define LOAD_A(buf, chunk) do {                                              \
        int _cg = (chunk);                                                   \
        _Pragma("unroll")                                                    \
        for (int _i = 0; _i < 4; ++_i) {                                     \
            int pos = t + 256 * _i;                                          \
            int row = pos >> 3;                                              \
            int cc  = pos & 7;                                               \
            const __nv_bfloat16* src = &g_FsT[(size_t)row * KPAD + _cg * 64 + cc * 8]; \
            uint32_t off = (uint32_t)(row * 128 + cc * 16);                  \
            CPA16((buf) + SWZ(off), src);                                    \
        }                                                                    \
    } while (0)

#define LDG_H(chunk) do {                                                    \
        int _n = (chunk) * 64 + krow;                                        \
        bool _v = _n < Nn;                                                   \
        const float* _hr = H + (size_t)_n * Ee;                              \
        _Pragma("unroll")                                                    \
        for (int _j = 0; _j < 4; ++_j) {                                     \
            float4 f;                                                        \
            if (!tail) {                                                     \
                f = _v ? __ldcg((const float4*)&_hr[e0 + ecol + 4 * _j])     \
                       : make_float4(0.f, 0.f, 0.f, 0.f);                    \
            } else {                                                         \
                int _e = e0 + ecol + 4 * _j;                                 \
                f.x = (_v && _e + 0 < Ee) ? __ldcg(&_hr[_e + 0]) : 0.f;      \
                f.y = (_v && _e + 1 < Ee) ? __ldcg(&_hr[_e + 1]) : 0.f;      \
                f.z = (_v && _e + 2 < Ee) ? __ldcg(&_hr[_e + 2]) : 0.f;      \
                f.w = (_v && _e + 3 < Ee) ? __ldcg(&_hr[_e + 3]) : 0.f;      \
            }                                                                \
            __nv_bfloat162 p0 = __floats2bfloat162_rn(f.x, f.y);             \
            __nv_bfloat162 p1 = __floats2bfloat162_rn(f.z, f.w);             \
            w[2 * _j]     = *(uint32_t*)&p0;                                 \
            w[2 * _j + 1] = *(uint32_t*)&p1;                                 \
        }                                                                    \
    } while (0)

#define STS_H(buf) do {                                                      \
        uint32_t off = (uint32_t)(krow * 128 + ecol * 2);                    \
        sts128((buf) + SWZ(off),      w[0], w[1], w[2], w[3]);               \
        sts128((buf) + SWZ(off + 16), w[4], w[5], w[6], w[7]);               \
    } while (0)

#define COMPUTE(abuf, bbuf) do {                                             \
        _Pragma("unroll")                                                    \
        for (int k0 = 0; k0 < 64; k0 += 16) {                                \
            uint32_t afr[2][4];                                              \
            _Pragma("unroll")                                                \
            for (int i = 0; i < 2; ++i) {                                    \
                uint32_t off = (uint32_t)((m0 + i * 16 + aRow) * 128         \
                                          + (k0 + aKh) * 2);                 \
                LDSM4(afr[i], (abuf) + SWZ(off));                            \
            }                                                                \
            uint32_t bfr[2][4];                                              \
            _Pragma("unroll")                                                \
            for (int jb = 0; jb < 2; ++jb) {                                 \
                uint32_t off = (uint32_t)((k0 + bKr) * 128                   \
                                          + (n0w + jb * 16 + bNc) * 2);      \
                LDSM4T(bfr[jb], (bbuf) + SWZ(off));                          \
            }                                                                \
            _Pragma("unroll")                                                \
            for (int i = 0; i < 2; ++i)                                      \
                _Pragma("unroll")                                            \
                for (int j = 0; j < 4; ++j)                                  \
                    mma16816(acc[i][j], afr[i],                              \
                             bfr[j >> 1][(j & 1) * 2],                       \
                             bfr[j >> 1][(j & 1) * 2 + 1]);                  \
        }                                                                    \
    } while (0)

    // ---- overlap: issue first H tile load BEFORE the prep spin barrier ----
    LDG_H(c0);

    // ---- global spin barrier (all 444 CTAs resident at occ 3 -> safe) ----
    if (t == 0) {
        while (atomicAdd(&g_prepdone, 0) < NPREP) {}
    }
    __syncthreads();
    __threadfence();

    // ---- pipeline (double-buffered) ----
    LOAD_A(sb, c0);
    CPA_COMMIT();
    CPA_WAIT0();
    STS_H(sb + 32768);
    __syncthreads();

    for (int cc = 0; cc < nch; ++cc) {
        const int b = cc & 1;
        const uint32_t aCur = sb + b * 16384;
        const uint32_t bCur = sb + 32768 + b * 8192;
        const uint32_t aNxt = sb + (b ^ 1) * 16384;
        const uint32_t bNxt = sb + 32768 + (b ^ 1) * 8192;
        const bool has = (cc + 1) < nch;
        if (has) {
            LOAD_A(aNxt, c0 + cc + 1);
            CPA_COMMIT();
            LDG_H(c0 + cc + 1);
        }
        COMPUTE(aCur, bCur);
        if (has) {
            CPA_WAIT0();
            STS_H(bNxt);
        }
        __syncthreads();
    }

    // ---- write partials as bf16: g_Mpart[sl][d][e] ----
    #pragma unroll
    for (int i = 0; i < 2; ++i) {
        #pragma unroll
        for (int j = 0; j < 4; ++j) {
            int d = m0 + i * 16 + (lane >> 2);
            int e = e0 + n0w + j * 8 + (lane & 3) * 2;
            size_t base = ((size_t)(sl * DD + d)) * EPITCH + e;
            __nv_bfloat162 p0 = __floats2bfloat162_rn(acc[i][j][0], acc[i][j][1]);
            __nv_bfloat162 p1 = __floats2bfloat162_rn(acc[i][j][2], acc[i][j][3]);
            *(uint32_t*)&g_Mpart[base] = *(uint32_t*)&p0;
            *(uint32_t*)&g_Mpart[base + (size_t)8 * EPITCH] = *(uint32_t*)&p1;
        }
    }

    // ================= phase 3: fused tile + final reduce =================
    __threadfence();
    __syncthreads();
    __shared__ int sLastTile;
    if (t == 0) {
        int c = atomicAdd(&g_tilecnt[et], 1);
        sLastTile = (c == nsl - 1);
        if (sLastTile) g_tilecnt[et] = 0;     // reset for next replay
    }
    __syncthreads();
    if (!sLastTile) return;

    {
        float* r = (float*)smem;
        __threadfence();                      // acquire side
        const int e = e0 + (t & 15) * 4;      // 16 e-groups of 4
        const int d0r = (t >> 4) * 8;         // 16 d-strips of 8
        float4 di = *(const float4*)&g_deinv[e];
        float sq = 0.f;
        #pragma unroll
        for (int dd = 0; dd < 8; ++dd) {
            int d = d0r + dd;
            float4 v = make_float4(0.f, 0.f, 0.f, 0.f);
            #pragma unroll
            for (int j = 0; j < NSL; ++j) {
                uint2 m = *(const uint2*)&g_Mpart[((size_t)(j * DD + d)) * EPITCH + e];
                float2 lo = __bfloat1622float2(*(__nv_bfloat162*)&m.x);
                float2 hi = __bfloat1622float2(*(__nv_bfloat162*)&m.y);
                v.x += lo.x; v.y += lo.y; v.z += hi.x; v.w += hi.y;
            }
            sq += v.x * v.x * di.x + v.y * v.y * di.y
                + v.z * v.z * di.z + v.w * v.w * di.w;
        }
        r[t] = sq;
        __syncthreads();
        #pragma unroll
        for (int s = 128; s > 0; s >>= 1) {
            if (t < s) r[t] += r[t + s];
            __syncthreads();
        }
        __shared__ int sLastAll;
        if (t == 0) {
            g_blocksum[et] = r[0];
            __threadfence();
            int dc = atomicAdd(&g_donecnt, 1);
            sLastAll = (dc == NTILES - 1);
            if (sLastAll) g_donecnt = 0;      // reset for next replay
        }
        __syncthreads();
        if (!sLastAll) return;

        // ---- final combine (single CTA) ----
        __threadfence();
        float a2 = 0.f;
        for (int i = t; i < NPREP; i += 256) a2 += g_f2sum[i];
        for (int i = t; i < NTILES; i += 256) a2 -= g_blocksum[i];
        r[t] = a2;
        __syncthreads();
        #pragma unroll
        for (int s = 128; s > 0; s >>= 1) {
            if (t < s) r[t] += r[t + s];
            __syncthreads();
        }
        if (t == 0) {
            out[0] = r[0] / (float)Nn;
            g_prepdone = 0;                   // reset for next replay
        }
    }
}

// ---------------- launch ------------------------------------------------------
extern "C" void kernel_launch(void* const* d_in, const int* in_sizes, int n_in,
                              void* d_out, int out_size) {
    const float* F  = (const float*)d_in[0];   // [N,128]
    const float* H  = (const float*)d_in[1];   // [N,E]
    const float* Dv = (const float*)d_in[2];   // [N,N]
    const float* De = (const float*)d_in[3];   // [E,E]
    float* out = (float*)d_out;

    int Nn = in_sizes[0] / DD;                 // 10000
    int Ee = in_sizes[1] / Nn;                 // 5000

    cudaFuncSetAttribute(gemm_kernel, cudaFuncAttributeMaxDynamicSharedMemorySize,
                         49152);

    gemm_kernel<<<444, 256, 49152>>>(H, F, Dv, De, out, Nn, Ee);
}